// round 2
// baseline (speedup 1.0000x reference)
#include <cuda_runtime.h>
#include <cuda_bf16.h>
#include <math.h>

#define B_ 2
#define S_ 4096
#define D_ 1024
#define H_ 16
#define HD_ 64
#define M_ 512
#define L_ 1024
#define HID_ 2816
#define NSTEP 8

// ---------------- scratch (static device globals; no allocs) ----------------
__device__ float g_om  [B_*M_*D_];
__device__ float g_om2 [B_*M_*D_];
__device__ float g_t   [B_*M_*D_];
__device__ float g_om3 [B_*M_*D_];
__device__ float g_h1  [B_*M_*HID_];
__device__ float g_h3  [B_*M_*HID_];
__device__ float g_tmp [B_*M_*D_];
__device__ float g_subx[B_*M_*D_];
__device__ float g_q   [B_*H_*M_*HD_];   // roped xq  (B,H,512,64)
__device__ float g_k   [B_*H_*L_*HD_];   // roped k   (B,H,1024,64)
__device__ float g_v   [B_*H_*L_*HD_];   // v         (B,H,1024,64)
__device__ float g_out [B_*S_*D_];       // stacked om_new chunks

// ---------------- SGEMM: C[M,N] = A[M,K] @ B[K,N] (row-major, fp32) ---------
// 64x64 block tile, BK=16, 256 threads, 4x4 per-thread microtile.
__global__ void __launch_bounds__(256) sgemm64(const float* __restrict__ A,
                                               const float* __restrict__ Bm,
                                               float* __restrict__ C,
                                               int Mr, int Nc, int Kd, int accum)
{
    __shared__ float As[16][64];
    __shared__ float Bs[16][64];
    const int tid  = threadIdx.x;
    const int bm0  = blockIdx.y * 64;
    const int bn0  = blockIdx.x * 64;
    const int tx4  = (tid & 15) * 4;
    const int ty4  = (tid >> 4) * 4;
    const int arow = tid >> 2;          // 0..63
    const int acol = (tid & 3) * 4;     // 0,4,8,12
    const int brow = tid >> 4;          // 0..15
    const int bcol = (tid & 15) * 4;    // 0..60

    const float* Ap = A  + (size_t)(bm0 + arow) * Kd + acol;
    const float* Bp = Bm + (size_t)brow * Nc + bn0 + bcol;

    float acc[4][4];
#pragma unroll
    for (int i = 0; i < 4; i++)
#pragma unroll
        for (int j = 0; j < 4; j++) acc[i][j] = 0.f;

    for (int k0 = 0; k0 < Kd; k0 += 16) {
        float4 a4 = *(const float4*)Ap;
        float4 b4 = *(const float4*)Bp;
        As[acol + 0][arow] = a4.x;
        As[acol + 1][arow] = a4.y;
        As[acol + 2][arow] = a4.z;
        As[acol + 3][arow] = a4.w;
        *(float4*)&Bs[brow][bcol] = b4;
        __syncthreads();
#pragma unroll
        for (int k = 0; k < 16; k++) {
            float4 av = *(const float4*)&As[k][ty4];
            float4 bv = *(const float4*)&Bs[k][tx4];
            acc[0][0] += av.x * bv.x; acc[0][1] += av.x * bv.y; acc[0][2] += av.x * bv.z; acc[0][3] += av.x * bv.w;
            acc[1][0] += av.y * bv.x; acc[1][1] += av.y * bv.y; acc[1][2] += av.y * bv.z; acc[1][3] += av.y * bv.w;
            acc[2][0] += av.z * bv.x; acc[2][1] += av.z * bv.y; acc[2][2] += av.z * bv.z; acc[2][3] += av.z * bv.w;
            acc[3][0] += av.w * bv.x; acc[3][1] += av.w * bv.y; acc[3][2] += av.w * bv.z; acc[3][3] += av.w * bv.w;
        }
        __syncthreads();
        Ap += 16;
        Bp += (size_t)16 * Nc;
    }

    float* Cp = C + (size_t)(bm0 + (tid >> 4) * 4) * Nc + bn0 + tx4;
#pragma unroll
    for (int i = 0; i < 4; i++) {
        float4 cv = make_float4(acc[i][0], acc[i][1], acc[i][2], acc[i][3]);
        float4* dst = (float4*)(Cp + (size_t)i * Nc);
        if (accum) {
            float4 o = *dst;
            cv.x += o.x; cv.y += o.y; cv.z += o.z; cv.w += o.w;
        }
        *dst = cv;
    }
}

// ---------------- rmsnorm over rows of length 1024 --------------------------
__global__ void __launch_bounds__(256) rmsnorm_kernel(const float* __restrict__ in,
                                                      const float* __restrict__ w,
                                                      float* __restrict__ out)
{
    const int row = blockIdx.x;
    const int t = threadIdx.x;
    float4 v = ((const float4*)(in + (size_t)row * D_))[t];
    float ss = v.x * v.x + v.y * v.y + v.z * v.z + v.w * v.w;
#pragma unroll
    for (int o = 16; o; o >>= 1) ss += __shfl_xor_sync(0xffffffffu, ss, o);
    __shared__ float sred[8];
    if ((t & 31) == 0) sred[t >> 5] = ss;
    __syncthreads();
    float tot = 0.f;
#pragma unroll
    for (int i = 0; i < 8; i++) tot += sred[i];
    float rs = rsqrtf(tot * (1.0f / (float)D_) + 1e-5f);
    float4 wv = ((const float4*)w)[t];
    float4 o = make_float4(v.x * rs * wv.x, v.y * rs * wv.y, v.z * rs * wv.z, v.w * rs * wv.w);
    ((float4*)(out + (size_t)row * D_))[t] = o;
}

// ---------------- g = silu(h1) * h3  (in-place into h1) ---------------------
__global__ void __launch_bounds__(256) silu_mul_kernel(float* __restrict__ h1,
                                                       const float* __restrict__ h3,
                                                       int n4)
{
    int i = blockIdx.x * 256 + threadIdx.x;
    if (i >= n4) return;
    float4 a = ((float4*)h1)[i];
    float4 b = ((const float4*)h3)[i];
    a.x = a.x / (1.f + __expf(-a.x)) * b.x;
    a.y = a.y / (1.f + __expf(-a.y)) * b.y;
    a.z = a.z / (1.f + __expf(-a.z)) * b.z;
    a.w = a.w / (1.f + __expf(-a.w)) * b.w;
    ((float4*)h1)[i] = a;
}

// ---------------- copy x chunk (b, soff+s, d) -> contiguous (b,s,d) ---------
__global__ void __launch_bounds__(256) gather_chunk(const float* __restrict__ x,
                                                    float* __restrict__ subx, int soff)
{
    int i = blockIdx.x * 256 + threadIdx.x;        // 262144 float4s
    int d4 = i & 255;
    int s = (i >> 8) & 511;
    int b = i >> 17;
    ((float4*)subx)[i] = ((const float4*)x)[((size_t)b * S_ + soff + s) * 256 + d4];
}

// ---------------- om0 = broadcast(origin_mem) -------------------------------
__global__ void __launch_bounds__(256) init_om(const float* __restrict__ om0)
{
    int i = blockIdx.x * 256 + threadIdx.x;        // 262144 float4s
    int d4 = i & 255;
    int s = (i >> 8) & 511;
    ((float4*)g_om)[i] = ((const float4*)om0)[s * 256 + d4];
}

// ---------------- rope + scatter (B*512,1024)->(B,H,Lout,64) ----------------
__global__ void __launch_bounds__(256) rope_scatter(const float* __restrict__ in,
                                                    const float* __restrict__ fcos,
                                                    const float* __restrict__ fsin,
                                                    float* __restrict__ out,
                                                    int Lout, int rowoff, int posoff)
{
    int i = blockIdx.x * 256 + threadIdx.x;        // B*512*16*32 = 524288
    int j = i & 31;
    int h = (i >> 5) & 15;
    int s = (i >> 9) & 511;
    int b = i >> 18;
    int pos = posoff + s;
    float c = fcos[pos * 32 + j];
    float sn = fsin[pos * 32 + j];
    float2 t = ((const float2*)in)[((size_t)(b * 512 + s) << 9) + (h << 5) + j];
    float2 o;
    o.x = t.x * c - t.y * sn;
    o.y = t.x * sn + t.y * c;
    ((float2*)out)[((size_t)(b * 16 + h) * Lout + rowoff + s) * 32 + j] = o;
}

// ---------------- scatter (B*512,1024)->(B,H,Lout,64), no rope --------------
__global__ void __launch_bounds__(256) scatter_v(const float* __restrict__ in,
                                                 float* __restrict__ out,
                                                 int Lout, int rowoff)
{
    int i = blockIdx.x * 256 + threadIdx.x;        // B*512*16*16 = 262144 float4s
    int d4 = i & 15;
    int h = (i >> 4) & 15;
    int s = (i >> 8) & 511;
    int b = i >> 17;
    float4 t = ((const float4*)in)[i];
    ((float4*)out)[((size_t)(b * 16 + h) * Lout + rowoff + s) * 16 + d4] = t;
}

// ---------------- fused causal attention (x-queries only) -------------------
// grid: (B*H, 4), block: 128 threads. Each thread owns one query row.
__global__ void __launch_bounds__(128) attn_kernel(const float* __restrict__ Q,
                                                   const float* __restrict__ K,
                                                   const float* __restrict__ V,
                                                   float* __restrict__ outBuf,
                                                   float* __restrict__ omNext,
                                                   int stepOff)
{
    __shared__ float Ksh[64 * 64];
    __shared__ float Vsh[64 * 64];
    const int bh = blockIdx.x;
    const int b = bh >> 4;
    const int h = bh & 15;
    const int r = threadIdx.x;
    const int qloc = blockIdx.y * 128 + r;
    const int p = M_ + qloc;                      // global causal position

    const float* qp = Q + ((size_t)bh * M_ + qloc) * 64;
    float q[64];
#pragma unroll
    for (int d = 0; d < 64; d += 4) {
        float4 t = *(const float4*)(qp + d);
        q[d] = t.x; q[d + 1] = t.y; q[d + 2] = t.z; q[d + 3] = t.w;
    }
    float O[64];
#pragma unroll
    for (int d = 0; d < 64; d++) O[d] = 0.f;
    float m = -1e30f, l = 0.f;

    const int nkt = (M_ + blockIdx.y * 128 + 127) / 64 + 1;  // key tiles for block
    const float* Kb = K + (size_t)bh * L_ * 64;
    const float* Vb = V + (size_t)bh * L_ * 64;

    for (int kt = 0; kt < nkt; kt++) {
        __syncthreads();
        const float4* Ks4 = (const float4*)(Kb + kt * 64 * 64);
        const float4* Vs4 = (const float4*)(Vb + kt * 64 * 64);
#pragma unroll
        for (int i = 0; i < 8; i++) {
            ((float4*)Ksh)[i * 128 + r] = Ks4[i * 128 + r];
            ((float4*)Vsh)[i * 128 + r] = Vs4[i * 128 + r];
        }
        __syncthreads();
        const int kbase = kt * 64;
#pragma unroll 1
        for (int c = 0; c < 4; c++) {
            float sreg[16];
            float mt = -1e30f;
#pragma unroll
            for (int j = 0; j < 16; j++) {
                const float* kr = Ksh + (c * 16 + j) * 64;
                float acc = 0.f;
#pragma unroll
                for (int d = 0; d < 64; d += 4) {
                    float4 k4 = *(const float4*)(kr + d);
                    acc += q[d] * k4.x + q[d + 1] * k4.y + q[d + 2] * k4.z + q[d + 3] * k4.w;
                }
                float sj = acc * 0.125f;
                if (kbase + c * 16 + j > p) sj = -1e30f;
                sreg[j] = sj;
                mt = fmaxf(mt, sj);
            }
            float mnew = fmaxf(m, mt);
            float corr = __expf(m - mnew);
            l *= corr;
#pragma unroll
            for (int d = 0; d < 64; d++) O[d] *= corr;
#pragma unroll
            for (int j = 0; j < 16; j++) {
                float pj = __expf(sreg[j] - mnew);
                l += pj;
                const float* vr = Vsh + (c * 16 + j) * 64;
#pragma unroll
                for (int d = 0; d < 64; d += 4) {
                    float4 v4 = *(const float4*)(vr + d);
                    O[d]     += pj * v4.x;
                    O[d + 1] += pj * v4.y;
                    O[d + 2] += pj * v4.z;
                    O[d + 3] += pj * v4.w;
                }
            }
            m = mnew;
        }
    }

    float inv = 1.0f / l;
    float* o1 = outBuf + ((size_t)b * S_ + stepOff + qloc) * D_ + h * 64;
    float* o2 = omNext + ((size_t)(b * M_ + qloc)) * D_ + h * 64;
#pragma unroll
    for (int d = 0; d < 64; d += 4) {
        float4 t = make_float4(O[d] * inv, O[d + 1] * inv, O[d + 2] * inv, O[d + 3] * inv);
        *(float4*)(o1 + d) = t;
        *(float4*)(o2 + d) = t;
    }
}

// ---------------- host driver ----------------------------------------------
static void launch_gemm(const float* A, const float* Bm, float* C,
                        int Mr, int Nc, int Kd, int accum)
{
    dim3 g(Nc / 64, Mr / 64);
    sgemm64<<<g, 256>>>(A, Bm, C, Mr, Nc, Kd, accum);
}

extern "C" void kernel_launch(void* const* d_in, const int* in_sizes, int n_in,
                              void* d_out, int out_size)
{
    (void)in_sizes; (void)n_in; (void)out_size;
    const float* x    = (const float*)d_in[0];
    const float* fcos = (const float*)d_in[1];
    const float* fsin = (const float*)d_in[2];
    const float* wq   = (const float*)d_in[3];
    const float* wk   = (const float*)d_in[4];
    const float* wv   = (const float*)d_in[5];
    const float* wo   = (const float*)d_in[6];
    const float* wm   = (const float*)d_in[7];
    const float* wkm  = (const float*)d_in[8];
    const float* wvm  = (const float*)d_in[9];
    const float* w1   = (const float*)d_in[10];
    const float* w3   = (const float*)d_in[11];
    const float* w2   = (const float*)d_in[12];
    const float* ffnw = (const float*)d_in[13];
    const float* memw = (const float*)d_in[14];
    const float* om0  = (const float*)d_in[15];
    float* outp = (float*)d_out;

    float *p_om, *p_om2, *p_t, *p_om3, *p_h1, *p_h3, *p_tmp, *p_subx, *p_q, *p_k, *p_v, *p_outb;
    cudaGetSymbolAddress((void**)&p_om,   g_om);
    cudaGetSymbolAddress((void**)&p_om2,  g_om2);
    cudaGetSymbolAddress((void**)&p_t,    g_t);
    cudaGetSymbolAddress((void**)&p_om3,  g_om3);
    cudaGetSymbolAddress((void**)&p_h1,   g_h1);
    cudaGetSymbolAddress((void**)&p_h3,   g_h3);
    cudaGetSymbolAddress((void**)&p_tmp,  g_tmp);
    cudaGetSymbolAddress((void**)&p_subx, g_subx);
    cudaGetSymbolAddress((void**)&p_q,    g_q);
    cudaGetSymbolAddress((void**)&p_k,    g_k);
    cudaGetSymbolAddress((void**)&p_v,    g_v);
    cudaGetSymbolAddress((void**)&p_outb, g_out);

    const int BM = B_ * M_;                 // 1024 rows
    init_om<<<1024, 256>>>(om0);

    for (int s = 0; s < NSTEP; s++) {
        // memory-token branch
        launch_gemm(p_om, wm, p_om2, BM, D_, D_, 0);
        rmsnorm_kernel<<<BM, 256>>>(p_om2, ffnw, p_t);
        launch_gemm(p_t, w1, p_h1, BM, HID_, D_, 0);
        launch_gemm(p_t, w3, p_h3, BM, HID_, D_, 0);
        silu_mul_kernel<<<(BM * HID_ / 4 + 255) / 256, 256>>>(p_h1, p_h3, BM * HID_ / 4);
        launch_gemm(p_h1, w2, p_om2, BM, D_, HID_, 1);        // om2 += ffn(...)
        rmsnorm_kernel<<<BM, 256>>>(p_om2, memw, p_om3);
        launch_gemm(p_om3, wkm, p_tmp, BM, D_, D_, 0);
        rope_scatter<<<2048, 256>>>(p_tmp, fcos, fsin, p_k, L_, 0, 0);
        launch_gemm(p_om3, wvm, p_tmp, BM, D_, D_, 0);
        scatter_v<<<1024, 256>>>(p_tmp, p_v, L_, 0);

        // x-token branch
        gather_chunk<<<1024, 256>>>(x, p_subx, s * M_);
        launch_gemm(p_subx, wq, p_tmp, BM, D_, D_, 0);
        rope_scatter<<<2048, 256>>>(p_tmp, fcos, fsin, p_q, M_, 0, M_);
        launch_gemm(p_subx, wk, p_tmp, BM, D_, D_, 0);
        rope_scatter<<<2048, 256>>>(p_tmp, fcos, fsin, p_k, L_, M_, M_);
        launch_gemm(p_subx, wv, p_tmp, BM, D_, D_, 0);
        scatter_v<<<1024, 256>>>(p_tmp, p_v, L_, M_);

        // attention (x queries only; mem queries are discarded by reference)
        attn_kernel<<<dim3(B_ * H_, 4), 128>>>(p_q, p_k, p_v, p_outb, p_om, s * M_);
    }

    // final projection: (B*S, D) @ wo
    launch_gemm(p_outb, wo, outp, B_ * S_, D_, D_, 0);
}

// round 3
// speedup vs baseline: 1.0062x; 1.0062x over previous
#include <cuda_runtime.h>
#include <cuda_bf16.h>
#include <math.h>

#define B_ 2
#define S_ 4096
#define D_ 1024
#define H_ 16
#define HD_ 64
#define M_ 512
#define L_ 1024
#define HID_ 2816
#define NSTEP 8

// ---------------- scratch (static device globals; no allocs) ----------------
__device__ float g_om  [B_*M_*D_];
__device__ float g_om2 [B_*M_*D_];
__device__ float g_t   [B_*M_*D_];
__device__ float g_om3 [B_*M_*D_];
__device__ float g_h1  [B_*M_*HID_];
__device__ float g_h3  [B_*M_*HID_];
__device__ float g_tmp [B_*M_*D_];
__device__ float g_subx[B_*M_*D_];
__device__ float g_q   [B_*H_*M_*HD_];   // roped xq  (B,H,512,64)
__device__ float g_k   [B_*H_*L_*HD_];   // roped k   (B,H,1024,64)
__device__ float g_v   [B_*H_*L_*HD_];   // v         (B,H,1024,64)
__device__ float g_out [B_*S_*D_];       // stacked om_new chunks

// ---------------- 3xTF32 tensor-core GEMM -----------------------------------
// C[M,N] = A[M,K] @ B[K,N], row-major fp32 in/out, fp32 accumulate.
// CTA tile 128x64, BK=16, 128 threads (4 warps, 2x2), warp tile 64x32,
// per warp 4x4 m16n8k8 tiles, 3 mma per tile-k8 (hi*hi, lo*hi, hi*lo).
#define GBM 128
#define GBN 64
#define GBK 16
#define APAD 20   // 16 + 4 pad -> conflict-free frag LDS
#define BPAD 20

__device__ __forceinline__ unsigned f2tf32(float x) {
    unsigned r;
    asm("cvt.rna.tf32.f32 %0, %1;" : "=r"(r) : "f"(x));
    return r;
}

__device__ __forceinline__ void mma_tf32(float& c0, float& c1, float& c2, float& c3,
                                         unsigned a0, unsigned a1, unsigned a2, unsigned a3,
                                         unsigned b0, unsigned b1)
{
    asm volatile("mma.sync.aligned.m16n8k8.row.col.f32.tf32.tf32.f32 "
                 "{%0,%1,%2,%3}, {%4,%5,%6,%7}, {%8,%9}, {%0,%1,%2,%3};"
                 : "+f"(c0), "+f"(c1), "+f"(c2), "+f"(c3)
                 : "r"(a0), "r"(a1), "r"(a2), "r"(a3), "r"(b0), "r"(b1));
}

__global__ void __launch_bounds__(128) gemm_tf32x3(const float* __restrict__ A,
                                                   const float* __restrict__ Bm,
                                                   float* __restrict__ C,
                                                   int Mr, int Nc, int Kd, int accum)
{
    __shared__ unsigned Ah[GBM][APAD];
    __shared__ unsigned Al[GBM][APAD];
    __shared__ unsigned Bh[GBN][BPAD];
    __shared__ unsigned Bl[GBN][BPAD];

    const int tid  = threadIdx.x;
    const int lane = tid & 31;
    const int wid  = tid >> 5;
    const int grp  = lane >> 2;       // 0..7
    const int qk   = lane & 3;        // 0..3
    const int wm   = (wid >> 1) * 64; // warp m offset in tile
    const int wn   = (wid & 1) * 32;  // warp n offset in tile
    const int bm0  = blockIdx.y * GBM;
    const int bn0  = blockIdx.x * GBN;

    float acc[4][4][4];
#pragma unroll
    for (int i = 0; i < 4; i++)
#pragma unroll
        for (int j = 0; j < 4; j++)
#pragma unroll
            for (int e = 0; e < 4; e++) acc[i][j][e] = 0.f;

    // A tile loads: 512 float4s, 4 per thread. j = tid + i*128; row=j>>2, col4=(j&3)*4
    // B tile loads: 256 float4s, 2 per thread. j = tid + i*128; k=j>>4, n4=(j&15)*4
    float4 aR[4], bR[2];
    const int nst = Kd / GBK;

    // prefetch stage 0
#pragma unroll
    for (int i = 0; i < 4; i++) {
        int j = tid + i * 128;
        aR[i] = *(const float4*)(A + (size_t)(bm0 + (j >> 2)) * Kd + (j & 3) * 4);
    }
#pragma unroll
    for (int i = 0; i < 2; i++) {
        int j = tid + i * 128;
        bR[i] = *(const float4*)(Bm + (size_t)(j >> 4) * Nc + bn0 + (j & 15) * 4);
    }

    for (int st = 0; st < nst; st++) {
        __syncthreads();
        // split + store to smem
#pragma unroll
        for (int i = 0; i < 4; i++) {
            int j = tid + i * 128;
            int row = j >> 2, c0 = (j & 3) * 4;
            float v[4] = {aR[i].x, aR[i].y, aR[i].z, aR[i].w};
#pragma unroll
            for (int e = 0; e < 4; e++) {
                unsigned h = f2tf32(v[e]);
                float lo = v[e] - __uint_as_float(h);
                Ah[row][c0 + e] = h;
                Al[row][c0 + e] = f2tf32(lo);
            }
        }
#pragma unroll
        for (int i = 0; i < 2; i++) {
            int j = tid + i * 128;
            int k = j >> 4, n4 = (j & 15) * 4;
            float v[4] = {bR[i].x, bR[i].y, bR[i].z, bR[i].w};
#pragma unroll
            for (int e = 0; e < 4; e++) {
                unsigned h = f2tf32(v[e]);
                float lo = v[e] - __uint_as_float(h);
                Bh[n4 + e][k] = h;
                Bl[n4 + e][k] = f2tf32(lo);
            }
        }
        __syncthreads();

        // prefetch next stage (overlap with compute)
        if (st + 1 < nst) {
            int kb = (st + 1) * GBK;
#pragma unroll
            for (int i = 0; i < 4; i++) {
                int j = tid + i * 128;
                aR[i] = *(const float4*)(A + (size_t)(bm0 + (j >> 2)) * Kd + kb + (j & 3) * 4);
            }
#pragma unroll
            for (int i = 0; i < 2; i++) {
                int j = tid + i * 128;
                bR[i] = *(const float4*)(Bm + (size_t)(kb + (j >> 4)) * Nc + bn0 + (j & 15) * 4);
            }
        }

#pragma unroll
        for (int s8 = 0; s8 < 2; s8++) {
            const int kc = s8 * 8 + qk;
            unsigned ah[4][4], al[4][4], bh[4][2], bl[4][2];
#pragma unroll
            for (int mt = 0; mt < 4; mt++) {
                int r = wm + mt * 16 + grp;
                ah[mt][0] = Ah[r][kc];     ah[mt][1] = Ah[r + 8][kc];
                ah[mt][2] = Ah[r][kc + 4]; ah[mt][3] = Ah[r + 8][kc + 4];
                al[mt][0] = Al[r][kc];     al[mt][1] = Al[r + 8][kc];
                al[mt][2] = Al[r][kc + 4]; al[mt][3] = Al[r + 8][kc + 4];
            }
#pragma unroll
            for (int nt = 0; nt < 4; nt++) {
                int n = wn + nt * 8 + grp;
                bh[nt][0] = Bh[n][kc]; bh[nt][1] = Bh[n][kc + 4];
                bl[nt][0] = Bl[n][kc]; bl[nt][1] = Bl[n][kc + 4];
            }
#pragma unroll
            for (int mt = 0; mt < 4; mt++)
#pragma unroll
                for (int nt = 0; nt < 4; nt++) {
                    float* c = acc[mt][nt];
                    mma_tf32(c[0], c[1], c[2], c[3],
                             ah[mt][0], ah[mt][1], ah[mt][2], ah[mt][3],
                             bh[nt][0], bh[nt][1]);
                    mma_tf32(c[0], c[1], c[2], c[3],
                             al[mt][0], al[mt][1], al[mt][2], al[mt][3],
                             bh[nt][0], bh[nt][1]);
                    mma_tf32(c[0], c[1], c[2], c[3],
                             ah[mt][0], ah[mt][1], ah[mt][2], ah[mt][3],
                             bl[nt][0], bl[nt][1]);
                }
        }
    }

    // epilogue
#pragma unroll
    for (int mt = 0; mt < 4; mt++) {
        int r0 = bm0 + wm + mt * 16 + grp;
#pragma unroll
        for (int nt = 0; nt < 4; nt++) {
            int c0 = bn0 + wn + nt * 8 + 2 * qk;
            float* c = acc[mt][nt];
            float2* p0 = (float2*)(C + (size_t)r0 * Nc + c0);
            float2* p1 = (float2*)(C + (size_t)(r0 + 8) * Nc + c0);
            float2 v0 = make_float2(c[0], c[1]);
            float2 v1 = make_float2(c[2], c[3]);
            if (accum) {
                float2 o0 = *p0, o1 = *p1;
                v0.x += o0.x; v0.y += o0.y; v1.x += o1.x; v1.y += o1.y;
            }
            *p0 = v0;
            *p1 = v1;
        }
    }
}

// ---------------- rmsnorm over rows of length 1024 --------------------------
__global__ void __launch_bounds__(256) rmsnorm_kernel(const float* __restrict__ in,
                                                      const float* __restrict__ w,
                                                      float* __restrict__ out)
{
    const int row = blockIdx.x;
    const int t = threadIdx.x;
    float4 v = ((const float4*)(in + (size_t)row * D_))[t];
    float ss = v.x * v.x + v.y * v.y + v.z * v.z + v.w * v.w;
#pragma unroll
    for (int o = 16; o; o >>= 1) ss += __shfl_xor_sync(0xffffffffu, ss, o);
    __shared__ float sred[8];
    if ((t & 31) == 0) sred[t >> 5] = ss;
    __syncthreads();
    float tot = 0.f;
#pragma unroll
    for (int i = 0; i < 8; i++) tot += sred[i];
    float rs = rsqrtf(tot * (1.0f / (float)D_) + 1e-5f);
    float4 wv = ((const float4*)w)[t];
    float4 o = make_float4(v.x * rs * wv.x, v.y * rs * wv.y, v.z * rs * wv.z, v.w * rs * wv.w);
    ((float4*)(out + (size_t)row * D_))[t] = o;
}

// ---------------- g = silu(h1) * h3  (in-place into h1) ---------------------
__global__ void __launch_bounds__(256) silu_mul_kernel(float* __restrict__ h1,
                                                       const float* __restrict__ h3,
                                                       int n4)
{
    int i = blockIdx.x * 256 + threadIdx.x;
    if (i >= n4) return;
    float4 a = ((float4*)h1)[i];
    float4 b = ((const float4*)h3)[i];
    a.x = a.x / (1.f + __expf(-a.x)) * b.x;
    a.y = a.y / (1.f + __expf(-a.y)) * b.y;
    a.z = a.z / (1.f + __expf(-a.z)) * b.z;
    a.w = a.w / (1.f + __expf(-a.w)) * b.w;
    ((float4*)h1)[i] = a;
}

// ---------------- copy x chunk (b, soff+s, d) -> contiguous (b,s,d) ---------
__global__ void __launch_bounds__(256) gather_chunk(const float* __restrict__ x,
                                                    float* __restrict__ subx, int soff)
{
    int i = blockIdx.x * 256 + threadIdx.x;        // 262144 float4s
    int d4 = i & 255;
    int s = (i >> 8) & 511;
    int b = i >> 17;
    ((float4*)subx)[i] = ((const float4*)x)[((size_t)b * S_ + soff + s) * 256 + d4];
}

// ---------------- om0 = broadcast(origin_mem) -------------------------------
__global__ void __launch_bounds__(256) init_om(const float* __restrict__ om0)
{
    int i = blockIdx.x * 256 + threadIdx.x;        // 262144 float4s
    int d4 = i & 255;
    int s = (i >> 8) & 511;
    ((float4*)g_om)[i] = ((const float4*)om0)[s * 256 + d4];
}

// ---------------- rope + scatter (B*512,1024)->(B,H,Lout,64) ----------------
__global__ void __launch_bounds__(256) rope_scatter(const float* __restrict__ in,
                                                    const float* __restrict__ fcos,
                                                    const float* __restrict__ fsin,
                                                    float* __restrict__ out,
                                                    int Lout, int rowoff, int posoff)
{
    int i = blockIdx.x * 256 + threadIdx.x;        // B*512*16*32 = 524288
    int j = i & 31;
    int h = (i >> 5) & 15;
    int s = (i >> 9) & 511;
    int b = i >> 18;
    int pos = posoff + s;
    float c = fcos[pos * 32 + j];
    float sn = fsin[pos * 32 + j];
    float2 t = ((const float2*)in)[((size_t)(b * 512 + s) << 9) + (h << 5) + j];
    float2 o;
    o.x = t.x * c - t.y * sn;
    o.y = t.x * sn + t.y * c;
    ((float2*)out)[((size_t)(b * 16 + h) * Lout + rowoff + s) * 32 + j] = o;
}

// ---------------- scatter (B*512,1024)->(B,H,Lout,64), no rope --------------
__global__ void __launch_bounds__(256) scatter_v(const float* __restrict__ in,
                                                 float* __restrict__ out,
                                                 int Lout, int rowoff)
{
    int i = blockIdx.x * 256 + threadIdx.x;        // B*512*16*16 = 262144 float4s
    int d4 = i & 15;
    int h = (i >> 4) & 15;
    int s = (i >> 8) & 511;
    int b = i >> 17;
    float4 t = ((const float4*)in)[i];
    ((float4*)out)[((size_t)(b * 16 + h) * Lout + rowoff + s) * 16 + d4] = t;
}

// ---------------- fused causal attention (x-queries only) -------------------
// grid: (B*H, 4), block: 128 threads. Each thread owns one query row.
__global__ void __launch_bounds__(128) attn_kernel(const float* __restrict__ Q,
                                                   const float* __restrict__ K,
                                                   const float* __restrict__ V,
                                                   float* __restrict__ outBuf,
                                                   float* __restrict__ omNext,
                                                   int stepOff)
{
    __shared__ float Ksh[64 * 64];
    __shared__ float Vsh[64 * 64];
    const int bh = blockIdx.x;
    const int b = bh >> 4;
    const int h = bh & 15;
    const int r = threadIdx.x;
    const int qloc = blockIdx.y * 128 + r;
    const int p = M_ + qloc;                      // global causal position

    const float* qp = Q + ((size_t)bh * M_ + qloc) * 64;
    float q[64];
#pragma unroll
    for (int d = 0; d < 64; d += 4) {
        float4 t = *(const float4*)(qp + d);
        q[d] = t.x; q[d + 1] = t.y; q[d + 2] = t.z; q[d + 3] = t.w;
    }
    float O[64];
#pragma unroll
    for (int d = 0; d < 64; d++) O[d] = 0.f;
    float m = -1e30f, l = 0.f;

    const int nkt = (M_ + blockIdx.y * 128 + 127) / 64 + 1;  // key tiles for block
    const float* Kb = K + (size_t)bh * L_ * 64;
    const float* Vb = V + (size_t)bh * L_ * 64;

    for (int kt = 0; kt < nkt; kt++) {
        __syncthreads();
        const float4* Ks4 = (const float4*)(Kb + kt * 64 * 64);
        const float4* Vs4 = (const float4*)(Vb + kt * 64 * 64);
#pragma unroll
        for (int i = 0; i < 8; i++) {
            ((float4*)Ksh)[i * 128 + r] = Ks4[i * 128 + r];
            ((float4*)Vsh)[i * 128 + r] = Vs4[i * 128 + r];
        }
        __syncthreads();
        const int kbase = kt * 64;
#pragma unroll 1
        for (int c = 0; c < 4; c++) {
            float sreg[16];
            float mt = -1e30f;
#pragma unroll
            for (int j = 0; j < 16; j++) {
                const float* kr = Ksh + (c * 16 + j) * 64;
                float acc = 0.f;
#pragma unroll
                for (int d = 0; d < 64; d += 4) {
                    float4 k4 = *(const float4*)(kr + d);
                    acc += q[d] * k4.x + q[d + 1] * k4.y + q[d + 2] * k4.z + q[d + 3] * k4.w;
                }
                float sj = acc * 0.125f;
                if (kbase + c * 16 + j > p) sj = -1e30f;
                sreg[j] = sj;
                mt = fmaxf(mt, sj);
            }
            float mnew = fmaxf(m, mt);
            float corr = __expf(m - mnew);
            l *= corr;
#pragma unroll
            for (int d = 0; d < 64; d++) O[d] *= corr;
#pragma unroll
            for (int j = 0; j < 16; j++) {
                float pj = __expf(sreg[j] - mnew);
                l += pj;
                const float* vr = Vsh + (c * 16 + j) * 64;
#pragma unroll
                for (int d = 0; d < 64; d += 4) {
                    float4 v4 = *(const float4*)(vr + d);
                    O[d]     += pj * v4.x;
                    O[d + 1] += pj * v4.y;
                    O[d + 2] += pj * v4.z;
                    O[d + 3] += pj * v4.w;
                }
            }
            m = mnew;
        }
    }

    float inv = 1.0f / l;
    float* o1 = outBuf + ((size_t)b * S_ + stepOff + qloc) * D_ + h * 64;
    float* o2 = omNext + ((size_t)(b * M_ + qloc)) * D_ + h * 64;
#pragma unroll
    for (int d = 0; d < 64; d += 4) {
        float4 t = make_float4(O[d] * inv, O[d + 1] * inv, O[d + 2] * inv, O[d + 3] * inv);
        *(float4*)(o1 + d) = t;
        *(float4*)(o2 + d) = t;
    }
}

// ---------------- host driver ----------------------------------------------
static void launch_gemm(const float* A, const float* Bm, float* C,
                        int Mr, int Nc, int Kd, int accum)
{
    dim3 g(Nc / GBN, Mr / GBM);
    gemm_tf32x3<<<g, 128>>>(A, Bm, C, Mr, Nc, Kd, accum);
}

extern "C" void kernel_launch(void* const* d_in, const int* in_sizes, int n_in,
                              void* d_out, int out_size)
{
    (void)in_sizes; (void)n_in; (void)out_size;
    const float* x    = (const float*)d_in[0];
    const float* fcos = (const float*)d_in[1];
    const float* fsin = (const float*)d_in[2];
    const float* wq   = (const float*)d_in[3];
    const float* wk   = (const float*)d_in[4];
    const float* wv   = (const float*)d_in[5];
    const float* wo   = (const float*)d_in[6];
    const float* wm   = (const float*)d_in[7];
    const float* wkm  = (const float*)d_in[8];
    const float* wvm  = (const float*)d_in[9];
    const float* w1   = (const float*)d_in[10];
    const float* w3   = (const float*)d_in[11];
    const float* w2   = (const float*)d_in[12];
    const float* ffnw = (const float*)d_in[13];
    const float* memw = (const float*)d_in[14];
    const float* om0  = (const float*)d_in[15];
    float* outp = (float*)d_out;

    float *p_om, *p_om2, *p_t, *p_om3, *p_h1, *p_h3, *p_tmp, *p_subx, *p_q, *p_k, *p_v, *p_outb;
    cudaGetSymbolAddress((void**)&p_om,   g_om);
    cudaGetSymbolAddress((void**)&p_om2,  g_om2);
    cudaGetSymbolAddress((void**)&p_t,    g_t);
    cudaGetSymbolAddress((void**)&p_om3,  g_om3);
    cudaGetSymbolAddress((void**)&p_h1,   g_h1);
    cudaGetSymbolAddress((void**)&p_h3,   g_h3);
    cudaGetSymbolAddress((void**)&p_tmp,  g_tmp);
    cudaGetSymbolAddress((void**)&p_subx, g_subx);
    cudaGetSymbolAddress((void**)&p_q,    g_q);
    cudaGetSymbolAddress((void**)&p_k,    g_k);
    cudaGetSymbolAddress((void**)&p_v,    g_v);
    cudaGetSymbolAddress((void**)&p_outb, g_out);

    const int BM = B_ * M_;                 // 1024 rows
    init_om<<<1024, 256>>>(om0);

    for (int s = 0; s < NSTEP; s++) {
        // memory-token branch
        launch_gemm(p_om, wm, p_om2, BM, D_, D_, 0);
        rmsnorm_kernel<<<BM, 256>>>(p_om2, ffnw, p_t);
        launch_gemm(p_t, w1, p_h1, BM, HID_, D_, 0);
        launch_gemm(p_t, w3, p_h3, BM, HID_, D_, 0);
        silu_mul_kernel<<<(BM * HID_ / 4 + 255) / 256, 256>>>(p_h1, p_h3, BM * HID_ / 4);
        launch_gemm(p_h1, w2, p_om2, BM, D_, HID_, 1);        // om2 += ffn(...)
        rmsnorm_kernel<<<BM, 256>>>(p_om2, memw, p_om3);
        launch_gemm(p_om3, wkm, p_tmp, BM, D_, D_, 0);
        rope_scatter<<<2048, 256>>>(p_tmp, fcos, fsin, p_k, L_, 0, 0);
        launch_gemm(p_om3, wvm, p_tmp, BM, D_, D_, 0);
        scatter_v<<<1024, 256>>>(p_tmp, p_v, L_, 0);

        // x-token branch
        gather_chunk<<<1024, 256>>>(x, p_subx, s * M_);
        launch_gemm(p_subx, wq, p_tmp, BM, D_, D_, 0);
        rope_scatter<<<2048, 256>>>(p_tmp, fcos, fsin, p_q, M_, 0, M_);
        launch_gemm(p_subx, wk, p_tmp, BM, D_, D_, 0);
        rope_scatter<<<2048, 256>>>(p_tmp, fcos, fsin, p_k, L_, M_, M_);
        launch_gemm(p_subx, wv, p_tmp, BM, D_, D_, 0);
        scatter_v<<<1024, 256>>>(p_tmp, p_v, L_, M_);

        // attention (x queries only; mem queries are discarded by reference)
        attn_kernel<<<dim3(B_ * H_, 4), 128>>>(p_q, p_k, p_v, p_outb, p_om, s * M_);
    }

    // final projection: (B*S, D) @ wo
    launch_gemm(p_outb, wo, outp, B_ * S_, D_, D_, 0);
}

// round 4
// speedup vs baseline: 1.7087x; 1.6981x over previous
#include <cuda_runtime.h>
#include <cuda_bf16.h>
#include <stdint.h>
#include <math.h>

#define B_ 2
#define S_ 4096
#define D_ 1024
#define H_ 16
#define HD_ 64
#define M_ 512
#define L_ 1024
#define HID_ 2816
#define NSTEP 8

// ---------------- scratch (static device globals; no allocs) ----------------
// weight splits (tf32 hi/lo stored as float bit patterns)
__device__ float g_wqkvh[D_*3*D_], g_wqkvl[D_*3*D_];     // [1024][3072] q|k|v
__device__ float g_w13h [D_*2*HID_], g_w13l [D_*2*HID_]; // [1024][5632] w1|w3
__device__ float g_wkvmh[D_*2*D_], g_wkvml[D_*2*D_];     // [1024][2048] wkm|wvm
__device__ float g_wmh  [D_*D_],  g_wml  [D_*D_];
__device__ float g_w2h  [HID_*D_], g_w2l [HID_*D_];
__device__ float g_woh  [D_*D_],  g_wol  [D_*D_];
__device__ float g_xh   [B_*S_*D_], g_xl [B_*S_*D_];
// activations
__device__ float g_xqkv [B_*S_*3*D_];                    // x@[wq|wk|wv]
__device__ float g_qall [NSTEP*B_*H_*M_*HD_];            // roped xq all steps
__device__ float g_kxall[NSTEP*B_*H_*M_*HD_];            // roped xk all steps
__device__ float g_vxall[NSTEP*B_*H_*M_*HD_];            // xv all steps
__device__ float g_omh[B_*M_*D_], g_oml[B_*M_*D_];
__device__ float g_om2[B_*M_*D_];
__device__ float g_th [B_*M_*D_], g_tl [B_*M_*D_];
__device__ float g_om3h[B_*M_*D_], g_om3l[B_*M_*D_];
__device__ float g_hbuf[B_*M_*2*HID_];                   // [1024][5632]
__device__ float g_gh [B_*M_*HID_], g_gl [B_*M_*HID_];
__device__ float g_kvtmp[B_*M_*2*D_];                    // [1024][2048] km|vm
__device__ float g_kmem[B_*H_*M_*HD_], g_vmem[B_*H_*M_*HD_];
__device__ float g_outh[B_*S_*D_], g_outl[B_*S_*D_];

// ---------------- helpers ----------------------------------------------------
__device__ __forceinline__ unsigned f2tf32(float x) {
    unsigned r;
    asm("cvt.rna.tf32.f32 %0, %1;" : "=r"(r) : "f"(x));
    return r;
}
__device__ __forceinline__ void splitf(float x, float& h, float& l) {
    unsigned u = f2tf32(x);
    h = __uint_as_float(u);
    l = __uint_as_float(f2tf32(x - h));
}
__device__ __forceinline__ void mma_tf32(float& c0, float& c1, float& c2, float& c3,
                                         unsigned a0, unsigned a1, unsigned a2, unsigned a3,
                                         unsigned b0, unsigned b1)
{
    asm volatile("mma.sync.aligned.m16n8k8.row.col.f32.tf32.tf32.f32 "
                 "{%0,%1,%2,%3}, {%4,%5,%6,%7}, {%8,%9}, {%0,%1,%2,%3};"
                 : "+f"(c0), "+f"(c1), "+f"(c2), "+f"(c3)
                 : "r"(a0), "r"(a1), "r"(a2), "r"(a3), "r"(b0), "r"(b1));
}
__device__ __forceinline__ void cpa16(uint32_t* dst, const float* src) {
    unsigned d = (unsigned)__cvta_generic_to_shared(dst);
    asm volatile("cp.async.cg.shared.global [%0], [%1], 16;" :: "r"(d), "l"(src));
}

// ---------------- 3xTF32 GEMM with pre-split inputs -------------------------
// C[M,N] = (Ah+Al)@(Bh+Bl), dropping lo*lo. Tile BMxBN(=64), BK=16, 128 thr.
// smem: A row-major stride 20, B k-major stride 72 (both conflict-free frags).
template<int BM>
__global__ void __launch_bounds__(128) gemm3t(const float* __restrict__ Agh,
                                              const float* __restrict__ Agl,
                                              const float* __restrict__ Bgh,
                                              const float* __restrict__ Bgl,
                                              float* __restrict__ C,
                                              int Nc, int Kd, int accum)
{
    constexpr int MT = BM / 32;
    extern __shared__ uint32_t sm[];
    uint32_t* sAh = sm;
    uint32_t* sAl = sAh + 2 * BM * 20;
    uint32_t* sBh = sAl + 2 * BM * 20;
    uint32_t* sBl = sBh + 2 * 16 * 72;

    const int tid = threadIdx.x, lane = tid & 31, wid = tid >> 5;
    const int grp = lane >> 2, qk = lane & 3;
    const int wm = (wid >> 1) * (BM / 2), wn = (wid & 1) * 32;
    const int bm0 = blockIdx.y * BM, bn0 = blockIdx.x * 64;

    float acc[MT][4][4];
#pragma unroll
    for (int i = 0; i < MT; i++)
#pragma unroll
        for (int j = 0; j < 4; j++)
#pragma unroll
            for (int e = 0; e < 4; e++) acc[i][j][e] = 0.f;

    auto issue = [&](int st, int k0) {
        uint32_t* dAh = sAh + st * BM * 20;
        uint32_t* dAl = sAl + st * BM * 20;
        uint32_t* dBh = sBh + st * 16 * 72;
        uint32_t* dBl = sBl + st * 16 * 72;
#pragma unroll
        for (int i = 0; i < BM / 32; i++) {
            int j = tid + i * 128;
            int row = j >> 2, kq = (j & 3) * 4;
            size_t go = (size_t)(bm0 + row) * Kd + k0 + kq;
            cpa16(dAh + row * 20 + kq, Agh + go);
            cpa16(dAl + row * 20 + kq, Agl + go);
        }
#pragma unroll
        for (int i = 0; i < 2; i++) {
            int j = tid + i * 128;
            int k = j >> 4, nq = (j & 15) * 4;
            size_t go = (size_t)(k0 + k) * Nc + bn0 + nq;
            cpa16(dBh + k * 72 + nq, Bgh + go);
            cpa16(dBl + k * 72 + nq, Bgl + go);
        }
        asm volatile("cp.async.commit_group;");
    };

    const int nst = Kd / 16;
    issue(0, 0);
    for (int st = 0; st < nst; st++) {
        if (st + 1 < nst) {
            issue((st + 1) & 1, (st + 1) * 16);
            asm volatile("cp.async.wait_group 1;");
        } else {
            asm volatile("cp.async.wait_group 0;");
        }
        __syncthreads();
        const uint32_t* pAh = sAh + (st & 1) * BM * 20;
        const uint32_t* pAl = sAl + (st & 1) * BM * 20;
        const uint32_t* pBh = sBh + (st & 1) * 16 * 72;
        const uint32_t* pBl = sBl + (st & 1) * 16 * 72;
#pragma unroll
        for (int s8 = 0; s8 < 2; s8++) {
            const int kc = s8 * 8 + qk;
            uint32_t ah[MT][4], al[MT][4], bh4[4][2], bl4[4][2];
#pragma unroll
            for (int mt = 0; mt < MT; mt++) {
                int r = wm + mt * 16 + grp;
                ah[mt][0] = pAh[r * 20 + kc];       ah[mt][1] = pAh[(r + 8) * 20 + kc];
                ah[mt][2] = pAh[r * 20 + kc + 4];   ah[mt][3] = pAh[(r + 8) * 20 + kc + 4];
                al[mt][0] = pAl[r * 20 + kc];       al[mt][1] = pAl[(r + 8) * 20 + kc];
                al[mt][2] = pAl[r * 20 + kc + 4];   al[mt][3] = pAl[(r + 8) * 20 + kc + 4];
            }
#pragma unroll
            for (int nt = 0; nt < 4; nt++) {
                int n = wn + nt * 8 + grp;
                bh4[nt][0] = pBh[kc * 72 + n]; bh4[nt][1] = pBh[(kc + 4) * 72 + n];
                bl4[nt][0] = pBl[kc * 72 + n]; bl4[nt][1] = pBl[(kc + 4) * 72 + n];
            }
#pragma unroll
            for (int mt = 0; mt < MT; mt++)
#pragma unroll
                for (int nt = 0; nt < 4; nt++) {
                    float* c = acc[mt][nt];
                    mma_tf32(c[0], c[1], c[2], c[3],
                             ah[mt][0], ah[mt][1], ah[mt][2], ah[mt][3],
                             bh4[nt][0], bh4[nt][1]);
                    mma_tf32(c[0], c[1], c[2], c[3],
                             al[mt][0], al[mt][1], al[mt][2], al[mt][3],
                             bh4[nt][0], bh4[nt][1]);
                    mma_tf32(c[0], c[1], c[2], c[3],
                             ah[mt][0], ah[mt][1], ah[mt][2], ah[mt][3],
                             bl4[nt][0], bl4[nt][1]);
                }
        }
        __syncthreads();
    }

#pragma unroll
    for (int mt = 0; mt < MT; mt++) {
        int r0 = bm0 + wm + mt * 16 + grp;
#pragma unroll
        for (int nt = 0; nt < 4; nt++) {
            int c0 = bn0 + wn + nt * 8 + 2 * qk;
            float* c = acc[mt][nt];
            float2* p0 = (float2*)(C + (size_t)r0 * Nc + c0);
            float2* p1 = (float2*)(C + (size_t)(r0 + 8) * Nc + c0);
            float2 v0 = make_float2(c[0], c[1]);
            float2 v1 = make_float2(c[2], c[3]);
            if (accum) {
                float2 o0 = *p0, o1 = *p1;
                v0.x += o0.x; v0.y += o0.y; v1.x += o1.x; v1.y += o1.y;
            }
            *p0 = v0;
            *p1 = v1;
        }
    }
}

// ---------------- splits + elementwise ---------------------------------------
__global__ void __launch_bounds__(256) split_strided(const float* __restrict__ src,
                                                     float* __restrict__ dh,
                                                     float* __restrict__ dl,
                                                     int cols, int dstride, int coff)
{
    int c = blockIdx.x * 256 + threadIdx.x;
    if (c >= cols) return;
    int row = blockIdx.y;
    float v = src[(size_t)row * cols + c];
    float h, l;
    splitf(v, h, l);
    dh[(size_t)row * dstride + coff + c] = h;
    dl[(size_t)row * dstride + coff + c] = l;
}

__global__ void __launch_bounds__(256) init_om_split(const float* __restrict__ om0)
{
    int t = blockIdx.x * 256 + threadIdx.x;     // 2*512*1024
    int d = t & 1023;
    int i = (t >> 10) & 511;
    float h, l;
    splitf(om0[i * 1024 + d], h, l);
    g_omh[t] = h; g_oml[t] = l;
}

__global__ void __launch_bounds__(256) rmsnorm_split(const float* __restrict__ in,
                                                     const float* __restrict__ w,
                                                     float* __restrict__ oh,
                                                     float* __restrict__ ol)
{
    const int row = blockIdx.x;
    const int t = threadIdx.x;
    float4 v = ((const float4*)(in + (size_t)row * D_))[t];
    float ss = v.x * v.x + v.y * v.y + v.z * v.z + v.w * v.w;
#pragma unroll
    for (int o = 16; o; o >>= 1) ss += __shfl_xor_sync(0xffffffffu, ss, o);
    __shared__ float sred[8];
    if ((t & 31) == 0) sred[t >> 5] = ss;
    __syncthreads();
    float tot = 0.f;
#pragma unroll
    for (int i = 0; i < 8; i++) tot += sred[i];
    float rs = rsqrtf(tot * (1.0f / (float)D_) + 1e-5f);
    float4 wv = ((const float4*)w)[t];
    float y[4] = {v.x * rs * wv.x, v.y * rs * wv.y, v.z * rs * wv.z, v.w * rs * wv.w};
    float4 hh, ll;
    splitf(y[0], hh.x, ll.x); splitf(y[1], hh.y, ll.y);
    splitf(y[2], hh.z, ll.z); splitf(y[3], hh.w, ll.w);
    ((float4*)(oh + (size_t)row * D_))[t] = hh;
    ((float4*)(ol + (size_t)row * D_))[t] = ll;
}

// g = silu(h[:, :2816]) * h[:, 2816:], emitted split
__global__ void __launch_bounds__(256) silu_split(const float* __restrict__ hb,
                                                  float* __restrict__ gh,
                                                  float* __restrict__ gl)
{
    int c4 = blockIdx.x * 256 + threadIdx.x;     // 0..703
    if (c4 >= HID_ / 4) return;
    int row = blockIdx.y;
    const float* rp = hb + (size_t)row * (2 * HID_);
    float4 a = ((const float4*)rp)[c4];
    float4 b = ((const float4*)(rp + HID_))[c4];
    float g[4];
    g[0] = a.x / (1.f + __expf(-a.x)) * b.x;
    g[1] = a.y / (1.f + __expf(-a.y)) * b.y;
    g[2] = a.z / (1.f + __expf(-a.z)) * b.z;
    g[3] = a.w / (1.f + __expf(-a.w)) * b.w;
    float4 hh, ll;
    splitf(g[0], hh.x, ll.x); splitf(g[1], hh.y, ll.y);
    splitf(g[2], hh.z, ll.z); splitf(g[3], hh.w, ll.w);
    ((float4*)(gh + (size_t)row * HID_))[c4] = hh;
    ((float4*)(gl + (size_t)row * HID_))[c4] = ll;
}

// ---------------- rope / scatter ---------------------------------------------
// All-steps xq/xk rope: in = g_xqkv col offset, pos = M_ + i (same every step)
__global__ void __launch_bounds__(256) rope_all(const float* __restrict__ fcos,
                                                const float* __restrict__ fsin,
                                                float* __restrict__ out, int colOff)
{
    int t = blockIdx.x * 256 + threadIdx.x;      // 8192*16*32 = 4194304
    int j = t & 31;
    int h = (t >> 5) & 15;
    int rowg = t >> 9;                           // 0..8191 = b*4096 + s*512 + i
    int i = rowg & 511;
    int s = (rowg >> 9) & 7;
    int b = rowg >> 12;
    int pos = M_ + i;
    float c = fcos[pos * 32 + j];
    float sn = fsin[pos * 32 + j];
    float2 v = *(const float2*)(g_xqkv + (size_t)rowg * 3072 + colOff + h * 64 + 2 * j);
    float2 o;
    o.x = v.x * c - v.y * sn;
    o.y = v.x * sn + v.y * c;
    *(float2*)(out + (size_t)s * (B_*H_*M_*HD_) + (((size_t)(b * 16 + h) * 512 + i) * 64 + 2 * j)) = o;
}

__global__ void __launch_bounds__(256) scatter_all_v()
{
    int t = blockIdx.x * 256 + threadIdx.x;      // 8192*256 f4 = 2097152
    int f = t & 255;
    int h = f >> 4, d4 = f & 15;
    int rowg = t >> 8;
    int i = rowg & 511;
    int s = (rowg >> 9) & 7;
    int b = rowg >> 12;
    float4 v = ((const float4*)g_xqkv)[(size_t)rowg * 768 + 512 + f];
    ((float4*)g_vxall)[(size_t)s * (B_*H_*M_*HD_/4) + ((size_t)(b * 16 + h) * 512 + i) * 16 + d4] = v;
}

// mem-branch rope/scatter: kvtmp[1024][2048] = km|vm
__global__ void __launch_bounds__(256) rope_mem(const float* __restrict__ fcos,
                                                const float* __restrict__ fsin)
{
    int t = blockIdx.x * 256 + threadIdx.x;      // 1024*16*32 = 524288
    int j = t & 31;
    int h = (t >> 5) & 15;
    int rowg = t >> 9;                           // 0..1023 = b*512+i
    int i = rowg & 511;
    int b = rowg >> 9;
    float c = fcos[i * 32 + j];
    float sn = fsin[i * 32 + j];
    float2 v = *(const float2*)(g_kvtmp + (size_t)rowg * 2048 + h * 64 + 2 * j);
    float2 o;
    o.x = v.x * c - v.y * sn;
    o.y = v.x * sn + v.y * c;
    *(float2*)(g_kmem + ((size_t)(b * 16 + h) * 512 + i) * 64 + 2 * j) = o;
}

__global__ void __launch_bounds__(256) scatter_vmem()
{
    int t = blockIdx.x * 256 + threadIdx.x;      // 1024*256 = 262144
    int f = t & 255;
    int h = f >> 4, d4 = f & 15;
    int rowg = t >> 8;
    int i = rowg & 511;
    int b = rowg >> 9;
    float4 v = ((const float4*)g_kvtmp)[(size_t)rowg * 512 + 256 + f];
    ((float4*)g_vmem)[((size_t)(b * 16 + h) * 512 + i) * 16 + d4] = v;
}

// ---------------- fused causal attention (x queries only) --------------------
// grid (B*H, 8), 128 thr: 64 rows/block, 2 threads/row (32-dim halves).
__global__ void __launch_bounds__(128) attn2(const float* __restrict__ Qs,
                                             const float* __restrict__ Kx,
                                             const float* __restrict__ Vx,
                                             int stepOff)
{
    __shared__ float Ksh[64 * 72];
    __shared__ float Vsh[64 * 72];
    const int bh = blockIdx.x;
    const int by = blockIdx.y;
    const int b = bh >> 4, h = bh & 15;
    const int tid = threadIdx.x;
    const int rl = tid >> 1;                    // row in block 0..63
    const int half = tid & 1;
    const int off = half * 36;                  // padded half offset
    const int qrow = by * 64 + rl;

    const float* qp = Qs + ((size_t)bh * 512 + qrow) * 64 + half * 32;
    float q[32];
#pragma unroll
    for (int d = 0; d < 32; d += 4) {
        float4 v = *(const float4*)(qp + d);
        q[d] = v.x; q[d + 1] = v.y; q[d + 2] = v.z; q[d + 3] = v.w;
    }
    float O[32];
#pragma unroll
    for (int d = 0; d < 32; d++) O[d] = 0.f;
    float m = -1e30f, l = 0.f;

    const int nkt = 9 + by;
    for (int kt = 0; kt < nkt; kt++) {
        const float* ksrc = (kt < 8) ? (g_kmem + ((size_t)bh * 512 + kt * 64) * 64)
                                     : (Kx + ((size_t)bh * 512 + (kt - 8) * 64) * 64);
        const float* vsrc = (kt < 8) ? (g_vmem + ((size_t)bh * 512 + kt * 64) * 64)
                                     : (Vx + ((size_t)bh * 512 + (kt - 8) * 64) * 64);
        __syncthreads();
#pragma unroll
        for (int i = 0; i < 8; i++) {
            int idx = i * 128 + tid;            // 1024 float4
            int row = idx >> 4, c4 = idx & 15;
            int dst = row * 72 + c4 * 4 + (c4 >= 8 ? 4 : 0);
            *(float4*)(Ksh + dst) = ((const float4*)ksrc)[idx];
            *(float4*)(Vsh + dst) = ((const float4*)vsrc)[idx];
        }
        __syncthreads();
        const bool diag = (kt == 8 + by);
#pragma unroll 1
        for (int c = 0; c < 4; c++) {
            float sreg[16];
            float mt = -1e30f;
#pragma unroll
            for (int j = 0; j < 16; j++) {
                const float* kr = Ksh + (c * 16 + j) * 72 + off;
                float p = 0.f;
#pragma unroll
                for (int d = 0; d < 32; d += 4) {
                    float4 k4 = *(const float4*)(kr + d);
                    p += q[d] * k4.x + q[d + 1] * k4.y + q[d + 2] * k4.z + q[d + 3] * k4.w;
                }
                p += __shfl_xor_sync(0xffffffffu, p, 1);
                float sj = p * 0.125f;
                if (diag && (c * 16 + j) > rl) sj = -1e30f;
                sreg[j] = sj;
                mt = fmaxf(mt, sj);
            }
            float mnew = fmaxf(m, mt);
            float corr = __expf(m - mnew);
            l *= corr;
#pragma unroll
            for (int d = 0; d < 32; d++) O[d] *= corr;
#pragma unroll
            for (int j = 0; j < 16; j++) {
                float pj = __expf(sreg[j] - mnew);
                l += pj;
                const float* vr = Vsh + (c * 16 + j) * 72 + off;
#pragma unroll
                for (int d = 0; d < 32; d += 4) {
                    float4 v4 = *(const float4*)(vr + d);
                    O[d]     += pj * v4.x;
                    O[d + 1] += pj * v4.y;
                    O[d + 2] += pj * v4.z;
                    O[d + 3] += pj * v4.w;
                }
            }
            m = mnew;
        }
    }

    float inv = 1.0f / l;
    size_t o1 = ((size_t)b * S_ + stepOff + qrow) * D_ + h * 64 + half * 32;
    size_t o2 = ((size_t)(b * 512 + qrow)) * D_ + h * 64 + half * 32;
#pragma unroll
    for (int d = 0; d < 32; d += 4) {
        float4 hh, ll;
        splitf(O[d] * inv,     hh.x, ll.x);
        splitf(O[d + 1] * inv, hh.y, ll.y);
        splitf(O[d + 2] * inv, hh.z, ll.z);
        splitf(O[d + 3] * inv, hh.w, ll.w);
        *(float4*)(g_outh + o1 + d) = hh;
        *(float4*)(g_outl + o1 + d) = ll;
        *(float4*)(g_omh + o2 + d) = hh;
        *(float4*)(g_oml + o2 + d) = ll;
    }
}

// ---------------- host driver ------------------------------------------------
static float* sym(const void* s) { void* p; cudaGetSymbolAddress(&p, s); return (float*)p; }

extern "C" void kernel_launch(void* const* d_in, const int* in_sizes, int n_in,
                              void* d_out, int out_size)
{
    (void)in_sizes; (void)n_in; (void)out_size;
    const float* x    = (const float*)d_in[0];
    const float* fcos = (const float*)d_in[1];
    const float* fsin = (const float*)d_in[2];
    const float* wq   = (const float*)d_in[3];
    const float* wk   = (const float*)d_in[4];
    const float* wv   = (const float*)d_in[5];
    const float* wo   = (const float*)d_in[6];
    const float* wm   = (const float*)d_in[7];
    const float* wkm  = (const float*)d_in[8];
    const float* wvm  = (const float*)d_in[9];
    const float* w1   = (const float*)d_in[10];
    const float* w3   = (const float*)d_in[11];
    const float* w2   = (const float*)d_in[12];
    const float* ffnw = (const float*)d_in[13];
    const float* memw = (const float*)d_in[14];
    const float* om0  = (const float*)d_in[15];
    float* outp = (float*)d_out;

    static bool attrDone = false;
    if (!attrDone) {
        cudaFuncSetAttribute(gemm3t<128>, cudaFuncAttributeMaxDynamicSharedMemorySize, 59392);
        cudaFuncSetAttribute(gemm3t<64>,  cudaFuncAttributeMaxDynamicSharedMemorySize, 38912);
        attrDone = true;
    }

    float *wqkvh = sym(g_wqkvh), *wqkvl = sym(g_wqkvl);
    float *w13h = sym(g_w13h), *w13l = sym(g_w13l);
    float *wkvmh = sym(g_wkvmh), *wkvml = sym(g_wkvml);
    float *wmh = sym(g_wmh), *wml = sym(g_wml);
    float *w2h = sym(g_w2h), *w2l = sym(g_w2l);
    float *woh = sym(g_woh), *wol = sym(g_wol);
    float *xh = sym(g_xh), *xl = sym(g_xl);
    float *xqkv = sym(g_xqkv);
    float *qall = sym(g_qall), *kxall = sym(g_kxall), *vxall = sym(g_vxall);
    float *omh = sym(g_omh), *oml = sym(g_oml), *om2 = sym(g_om2);
    float *th = sym(g_th), *tl = sym(g_tl);
    float *om3h = sym(g_om3h), *om3l = sym(g_om3l);
    float *hbuf = sym(g_hbuf);
    float *gh = sym(g_gh), *gl = sym(g_gl);
    float *kvtmp = sym(g_kvtmp);
    float *outh = sym(g_outh), *outl = sym(g_outl);

    // ---- weight / input splits (once per launch) ----
    dim3 s1k(4, 1024);
    split_strided<<<s1k, 256>>>(wq,  wqkvh, wqkvl, 1024, 3072, 0);
    split_strided<<<s1k, 256>>>(wk,  wqkvh, wqkvl, 1024, 3072, 1024);
    split_strided<<<s1k, 256>>>(wv,  wqkvh, wqkvl, 1024, 3072, 2048);
    split_strided<<<dim3(11, 1024), 256>>>(w1, w13h, w13l, 2816, 5632, 0);
    split_strided<<<dim3(11, 1024), 256>>>(w3, w13h, w13l, 2816, 5632, 2816);
    split_strided<<<s1k, 256>>>(wkm, wkvmh, wkvml, 1024, 2048, 0);
    split_strided<<<s1k, 256>>>(wvm, wkvmh, wkvml, 1024, 2048, 1024);
    split_strided<<<s1k, 256>>>(wm,  wmh, wml, 1024, 1024, 0);
    split_strided<<<dim3(4, 2816), 256>>>(w2, w2h, w2l, 1024, 1024, 0);
    split_strided<<<s1k, 256>>>(wo,  woh, wol, 1024, 1024, 0);
    split_strided<<<dim3(4, 8192), 256>>>(x, xh, xl, 1024, 1024, 0);
    init_om_split<<<4096, 256>>>(om0);

    // ---- batched x-branch: xqkv = x @ [wq|wk|wv], rope/scatter all steps ----
    gemm3t<128><<<dim3(48, 64), 128, 59392>>>(xh, xl, wqkvh, wqkvl, xqkv, 3072, 1024, 0);
    rope_all<<<16384, 256>>>(fcos, fsin, qall, 0);
    rope_all<<<16384, 256>>>(fcos, fsin, kxall, 1024);
    scatter_all_v<<<8192, 256>>>();

    const size_t stepSz = (size_t)B_ * H_ * M_ * HD_;
    for (int s = 0; s < NSTEP; s++) {
        gemm3t<64><<<dim3(16, 16), 128, 38912>>>(omh, oml, wmh, wml, om2, 1024, 1024, 0);
        rmsnorm_split<<<1024, 256>>>(om2, ffnw, th, tl);
        gemm3t<128><<<dim3(88, 8), 128, 59392>>>(th, tl, w13h, w13l, hbuf, 5632, 1024, 0);
        silu_split<<<dim3(3, 1024), 256>>>(hbuf, gh, gl);
        gemm3t<64><<<dim3(16, 16), 128, 38912>>>(gh, gl, w2h, w2l, om2, 1024, 2816, 1);
        rmsnorm_split<<<1024, 256>>>(om2, memw, om3h, om3l);
        gemm3t<128><<<dim3(32, 8), 128, 59392>>>(om3h, om3l, wkvmh, wkvml, kvtmp, 2048, 1024, 0);
        rope_mem<<<2048, 256>>>(fcos, fsin);
        scatter_vmem<<<1024, 256>>>();
        attn2<<<dim3(B_ * H_, 8), 128>>>(qall + s * stepSz, kxall + s * stepSz,
                                         vxall + s * stepSz, s * M_);
    }

    // ---- final projection ----
    gemm3t<128><<<dim3(16, 64), 128, 59392>>>(outh, outl, woh, wol, outp, 1024, 1024, 0);
}

// round 10
// speedup vs baseline: 2.6225x; 1.5348x over previous
#include <cuda_runtime.h>
#include <cuda_fp16.h>
#include <stdint.h>
#include <math.h>

#define B_ 2
#define S_ 4096
#define D_ 1024
#define H_ 16
#define HD_ 64
#define M_ 512
#define L_ 1024
#define HID_ 2816
#define NSTEP 8

// ---------------- scratch (static device globals; no allocs) ----------------
// transposed+split weights, fp16 hi / scaled-lo: layout [N][K]
__device__ __align__(16) __half g_wqkvTh[3*D_*D_], g_wqkvTl[3*D_*D_];
__device__ __align__(16) __half g_w13Th [2*HID_*D_], g_w13Tl [2*HID_*D_];
__device__ __align__(16) __half g_wkvmTh[2*D_*D_], g_wkvmTl[2*D_*D_];
__device__ __align__(16) __half g_wmTh  [D_*D_],  g_wmTl  [D_*D_];
__device__ __align__(16) __half g_w2Th  [D_*HID_], g_w2Tl [D_*HID_];
__device__ __align__(16) __half g_woTh  [D_*D_],  g_woTl  [D_*D_];
// activations (A operands), fp16 hi/lo
__device__ __align__(16) __half g_xh [B_*S_*D_],  g_xl [B_*S_*D_];
__device__ __align__(16) __half g_omh[B_*M_*D_],  g_oml[B_*M_*D_];
__device__ __align__(16) __half g_th [B_*M_*D_],  g_tl [B_*M_*D_];
__device__ __align__(16) __half g_om3h[B_*M_*D_], g_om3l[B_*M_*D_];
__device__ __align__(16) __half g_gh [B_*M_*HID_], g_gl [B_*M_*HID_];
__device__ __align__(16) __half g_outh[B_*S_*D_], g_outl[B_*S_*D_];
// fp32 activations
__device__ float g_xqkv [B_*S_*3*D_];
__device__ float g_qall [NSTEP*B_*H_*M_*HD_];
__device__ float g_kxall[NSTEP*B_*H_*M_*HD_];
__device__ float g_vxall[NSTEP*B_*H_*M_*HD_];
__device__ float g_om2  [B_*M_*D_];
__device__ float g_hbuf [B_*M_*2*HID_];
__device__ float g_kvtmp[B_*M_*2*D_];
__device__ float g_kmem [B_*H_*M_*HD_], g_vmem[B_*H_*M_*HD_];

// ---------------- helpers ----------------------------------------------------
__device__ __forceinline__ void splith(float v, __half& h, __half& l) {
    h = __float2half_rn(v);
    l = __float2half_rn((v - __half2float(h)) * 2048.0f);
}

__device__ __forceinline__ void hmma(float* c, const uint32_t* a, const uint32_t* b)
{
    asm volatile("mma.sync.aligned.m16n8k16.row.col.f32.f16.f16.f32 "
                 "{%0,%1,%2,%3}, {%4,%5,%6,%7}, {%8,%9}, {%0,%1,%2,%3};"
                 : "+f"(c[0]), "+f"(c[1]), "+f"(c[2]), "+f"(c[3])
                 : "r"(a[0]), "r"(a[1]), "r"(a[2]), "r"(a[3]), "r"(b[0]), "r"(b[1]));
}

__device__ __forceinline__ void cpa16(uint8_t* dst, const void* src) {
    unsigned d = (unsigned)__cvta_generic_to_shared(dst);
    asm volatile("cp.async.cg.shared.global [%0], [%1], 16;" :: "r"(d), "l"(src));
}

// ---------------- fp16-split tensor GEMM (mma.sync) --------------------------
// C[M,Ntot] = (Ah + Al/2048) @ (Bh + Bl/2048)^T
//   A: [M][K] halves hi/lo (K-major); B: [Ntot][K] halves hi/lo (= W^T)
//   acc0 += Ah·Bh ; acc1 += Ah·Bl + Al·Bh ; C = acc0 + acc1/2048
// CTA tile 128x64, BK=32 halves, 256 threads (8 warps, 4x2), warp tile 32x32.
#define HBM 128
#define HBN 64
#define HBK 32
#define ROWB 80            // bytes per smem row (32 halves + 8 pad)
#define AH0 0
#define AH1 10240
#define AL0 20480
#define AL1 30720
#define BH0 40960
#define BH1 46080
#define BL0 51200
#define BL1 56320
#define HSM_BYTES 61440

__global__ void __launch_bounds__(256, 2)
gemm_hs(const __half* __restrict__ Ah, const __half* __restrict__ Al,
        const __half* __restrict__ Bh, const __half* __restrict__ Bl,
        float* __restrict__ C, int Ntot, int K, int accum)
{
    extern __shared__ uint8_t dyn[];
    const int tid = threadIdx.x, lane = tid & 31, wid = tid >> 5;
    const int grp = lane >> 2, qk = lane & 3;
    const int wm = (wid >> 1) * 32, wn = (wid & 1) * 32;
    const int bm0 = blockIdx.y * HBM, bn0 = blockIdx.x * HBN;

    float acc0[2][4][4], acc1[2][4][4];
#pragma unroll
    for (int i = 0; i < 2; i++)
#pragma unroll
        for (int j = 0; j < 4; j++)
#pragma unroll
            for (int e = 0; e < 4; e++) { acc0[i][j][e] = 0.f; acc1[i][j][e] = 0.f; }

    auto issue = [&](int ci) {
        int b = ci & 1;
        int k0 = ci * HBK;
        uint8_t* dAh = dyn + (b ? AH1 : AH0);
        uint8_t* dAl = dyn + (b ? AL1 : AL0);
        uint8_t* dBh = dyn + (b ? BH1 : BH0);
        uint8_t* dBl = dyn + (b ? BL1 : BL0);
#pragma unroll
        for (int i = 0; i < 2; i++) {
            int idx = tid + i * 256;            // 512 chunks of 16B
            int row = idx >> 2, c16 = idx & 3;
            size_t go = (size_t)(bm0 + row) * K + k0 + c16 * 8;
            cpa16(dAh + row * ROWB + c16 * 16, Ah + go);
            cpa16(dAl + row * ROWB + c16 * 16, Al + go);
        }
        {
            int row = tid >> 2, c16 = tid & 3;  // 256 chunks
            size_t go = (size_t)(bn0 + row) * K + k0 + c16 * 8;
            cpa16(dBh + row * ROWB + c16 * 16, Bh + go);
            cpa16(dBl + row * ROWB + c16 * 16, Bl + go);
        }
        asm volatile("cp.async.commit_group;");
    };

    const int nch = K / HBK;
    issue(0);
    for (int st = 0; st < nch; st++) {
        if (st + 1 < nch) {
            issue(st + 1);
            asm volatile("cp.async.wait_group 1;");
        } else {
            asm volatile("cp.async.wait_group 0;");
        }
        __syncthreads();
        int b = st & 1;
        const uint8_t* pAh = dyn + (b ? AH1 : AH0);
        const uint8_t* pAl = dyn + (b ? AL1 : AL0);
        const uint8_t* pBh = dyn + (b ? BH1 : BH0);
        const uint8_t* pBl = dyn + (b ? BL1 : BL0);
#pragma unroll
        for (int s16 = 0; s16 < 2; s16++) {
            const int cb0 = s16 * 32 + qk * 4;   // byte offset of k-pair
            uint32_t ah[2][4], al[2][4], bh[4][2], bl[4][2];
#pragma unroll
            for (int mt = 0; mt < 2; mt++) {
                int r = wm + mt * 16 + grp;
                ah[mt][0] = *(const uint32_t*)(pAh + r * ROWB + cb0);
                ah[mt][1] = *(const uint32_t*)(pAh + (r + 8) * ROWB + cb0);
                ah[mt][2] = *(const uint32_t*)(pAh + r * ROWB + cb0 + 16);
                ah[mt][3] = *(const uint32_t*)(pAh + (r + 8) * ROWB + cb0 + 16);
                al[mt][0] = *(const uint32_t*)(pAl + r * ROWB + cb0);
                al[mt][1] = *(const uint32_t*)(pAl + (r + 8) * ROWB + cb0);
                al[mt][2] = *(const uint32_t*)(pAl + r * ROWB + cb0 + 16);
                al[mt][3] = *(const uint32_t*)(pAl + (r + 8) * ROWB + cb0 + 16);
            }
#pragma unroll
            for (int nt = 0; nt < 4; nt++) {
                int n = wn + nt * 8 + grp;
                bh[nt][0] = *(const uint32_t*)(pBh + n * ROWB + cb0);
                bh[nt][1] = *(const uint32_t*)(pBh + n * ROWB + cb0 + 16);
                bl[nt][0] = *(const uint32_t*)(pBl + n * ROWB + cb0);
                bl[nt][1] = *(const uint32_t*)(pBl + n * ROWB + cb0 + 16);
            }
#pragma unroll
            for (int mt = 0; mt < 2; mt++)
#pragma unroll
                for (int nt = 0; nt < 4; nt++) {
                    hmma(acc0[mt][nt], ah[mt], bh[nt]);
                    hmma(acc1[mt][nt], ah[mt], bl[nt]);
                    hmma(acc1[mt][nt], al[mt], bh[nt]);
                }
        }
        __syncthreads();
    }

    const float isc = 4.8828125e-4f;   // 1/2048
#pragma unroll
    for (int mt = 0; mt < 2; mt++) {
        int r0 = bm0 + wm + mt * 16 + grp;
#pragma unroll
        for (int nt = 0; nt < 4; nt++) {
            int c0 = bn0 + wn + nt * 8 + 2 * qk;
            float v0 = acc0[mt][nt][0] + acc1[mt][nt][0] * isc;
            float v1 = acc0[mt][nt][1] + acc1[mt][nt][1] * isc;
            float v2 = acc0[mt][nt][2] + acc1[mt][nt][2] * isc;
            float v3 = acc0[mt][nt][3] + acc1[mt][nt][3] * isc;
            float2* p0 = (float2*)(C + (size_t)r0 * Ntot + c0);
            float2* p1 = (float2*)(C + (size_t)(r0 + 8) * Ntot + c0);
            float2 w0 = make_float2(v0, v1), w1 = make_float2(v2, v3);
            if (accum) {
                float2 o0 = *p0, o1 = *p1;
                w0.x += o0.x; w0.y += o0.y; w1.x += o1.x; w1.y += o1.y;
            }
            *p0 = w0;
            *p1 = w1;
        }
    }
}

// ---------------- weight transpose + split: w[K][N] -> out[N][K] -------------
__global__ void __launch_bounds__(256) wsplitT(const float* __restrict__ w,
                                               __half* __restrict__ bh,
                                               __half* __restrict__ bl,
                                               int K, int N)
{
    __shared__ float t[32][33];
    int n0 = blockIdx.x * 32, k0 = blockIdx.y * 32;
    int tx = threadIdx.x & 31, ty = threadIdx.x >> 5;
#pragma unroll
    for (int i = 0; i < 4; i++)
        t[ty + i * 8][tx] = w[(size_t)(k0 + ty + i * 8) * N + n0 + tx];
    __syncthreads();
#pragma unroll
    for (int i = 0; i < 4; i++) {
        int nn = ty + i * 8;
        float v = t[tx][nn];
        __half h, l;
        splith(v, h, l);
        bh[(size_t)(n0 + nn) * K + k0 + tx] = h;
        bl[(size_t)(n0 + nn) * K + k0 + tx] = l;
    }
}

// ---------------- activation split (no transpose) ----------------------------
__global__ void __launch_bounds__(256) asplit(const float* __restrict__ in,
                                              __half* __restrict__ oh,
                                              __half* __restrict__ ol, int n4)
{
    int i = blockIdx.x * 256 + threadIdx.x;
    if (i >= n4) return;
    float4 v = ((const float4*)in)[i];
    __half h0, l0, h1, l1, h2, l2, h3, l3;
    splith(v.x, h0, l0); splith(v.y, h1, l1);
    splith(v.z, h2, l2); splith(v.w, h3, l3);
    ((__half2*)oh)[i * 2]     = __halves2half2(h0, h1);
    ((__half2*)oh)[i * 2 + 1] = __halves2half2(h2, h3);
    ((__half2*)ol)[i * 2]     = __halves2half2(l0, l1);
    ((__half2*)ol)[i * 2 + 1] = __halves2half2(l2, l3);
}

__global__ void __launch_bounds__(256) init_om_split(const float* __restrict__ om0)
{
    int t = blockIdx.x * 256 + threadIdx.x;     // 2*512*1024
    int d = t & 1023;
    int i = (t >> 10) & 511;
    __half h, l;
    splith(om0[i * 1024 + d], h, l);
    g_omh[t] = h; g_oml[t] = l;
}

// ---------------- rmsnorm -> split -------------------------------------------
__global__ void __launch_bounds__(256) rmsnorm_split(const float* __restrict__ in,
                                                     const float* __restrict__ w,
                                                     __half* __restrict__ oh,
                                                     __half* __restrict__ ol)
{
    const int row = blockIdx.x;
    const int t = threadIdx.x;
    float4 v = ((const float4*)(in + (size_t)row * D_))[t];
    float ss = v.x * v.x + v.y * v.y + v.z * v.z + v.w * v.w;
#pragma unroll
    for (int o = 16; o; o >>= 1) ss += __shfl_xor_sync(0xffffffffu, ss, o);
    __shared__ float sred[8];
    if ((t & 31) == 0) sred[t >> 5] = ss;
    __syncthreads();
    float tot = 0.f;
#pragma unroll
    for (int i = 0; i < 8; i++) tot += sred[i];
    float rs = rsqrtf(tot * (1.0f / (float)D_) + 1e-5f);
    float4 wv = ((const float4*)w)[t];
    float y0 = v.x * rs * wv.x, y1 = v.y * rs * wv.y;
    float y2 = v.z * rs * wv.z, y3 = v.w * rs * wv.w;
    __half h0, l0, h1, l1, h2, l2, h3, l3;
    splith(y0, h0, l0); splith(y1, h1, l1); splith(y2, h2, l2); splith(y3, h3, l3);
    __half2* ph = (__half2*)(oh + (size_t)row * D_);
    __half2* pl = (__half2*)(ol + (size_t)row * D_);
    ph[t * 2]     = __halves2half2(h0, h1);
    ph[t * 2 + 1] = __halves2half2(h2, h3);
    pl[t * 2]     = __halves2half2(l0, l1);
    pl[t * 2 + 1] = __halves2half2(l2, l3);
}

// ---------------- silu -> split ----------------------------------------------
__global__ void __launch_bounds__(256) silu_split(const float* __restrict__ hb,
                                                  __half* __restrict__ gh,
                                                  __half* __restrict__ gl)
{
    int c4 = blockIdx.x * 256 + threadIdx.x;     // 0..703
    if (c4 >= HID_ / 4) return;
    int row = blockIdx.y;
    const float* rp = hb + (size_t)row * (2 * HID_);
    float4 a = ((const float4*)rp)[c4];
    float4 b = ((const float4*)(rp + HID_))[c4];
    float g0 = a.x / (1.f + __expf(-a.x)) * b.x;
    float g1 = a.y / (1.f + __expf(-a.y)) * b.y;
    float g2 = a.z / (1.f + __expf(-a.z)) * b.z;
    float g3 = a.w / (1.f + __expf(-a.w)) * b.w;
    __half h0, l0, h1, l1, h2, l2, h3, l3;
    splith(g0, h0, l0); splith(g1, h1, l1); splith(g2, h2, l2); splith(g3, h3, l3);
    __half2* ph = (__half2*)(gh + (size_t)row * HID_);
    __half2* pl = (__half2*)(gl + (size_t)row * HID_);
    ph[c4 * 2]     = __halves2half2(h0, h1);
    ph[c4 * 2 + 1] = __halves2half2(h2, h3);
    pl[c4 * 2]     = __halves2half2(l0, l1);
    pl[c4 * 2 + 1] = __halves2half2(l2, l3);
}

// ---------------- rope / scatter ---------------------------------------------
__global__ void __launch_bounds__(256) rope_all(const float* __restrict__ fcos,
                                                const float* __restrict__ fsin,
                                                float* __restrict__ out, int colOff)
{
    int t = blockIdx.x * 256 + threadIdx.x;      // 4194304
    int j = t & 31;
    int h = (t >> 5) & 15;
    int rowg = t >> 9;
    int i = rowg & 511;
    int s = (rowg >> 9) & 7;
    int b = rowg >> 12;
    int pos = M_ + i;
    float c = fcos[pos * 32 + j];
    float sn = fsin[pos * 32 + j];
    float2 v = *(const float2*)(g_xqkv + (size_t)rowg * 3072 + colOff + h * 64 + 2 * j);
    float2 o;
    o.x = v.x * c - v.y * sn;
    o.y = v.x * sn + v.y * c;
    *(float2*)(out + (size_t)s * (B_*H_*M_*HD_) + (((size_t)(b * 16 + h) * 512 + i) * 64 + 2 * j)) = o;
}

__global__ void __launch_bounds__(256) scatter_all_v()
{
    int t = blockIdx.x * 256 + threadIdx.x;      // 2097152
    int f = t & 255;
    int h = f >> 4, d4 = f & 15;
    int rowg = t >> 8;
    int i = rowg & 511;
    int s = (rowg >> 9) & 7;
    int b = rowg >> 12;
    float4 v = ((const float4*)g_xqkv)[(size_t)rowg * 768 + 512 + f];
    ((float4*)g_vxall)[(size_t)s * (B_*H_*M_*HD_/4) + ((size_t)(b * 16 + h) * 512 + i) * 16 + d4] = v;
}

__global__ void __launch_bounds__(256) rope_mem(const float* __restrict__ fcos,
                                                const float* __restrict__ fsin)
{
    int t = blockIdx.x * 256 + threadIdx.x;      // 524288
    int j = t & 31;
    int h = (t >> 5) & 15;
    int rowg = t >> 9;
    int i = rowg & 511;
    int b = rowg >> 9;
    float c = fcos[i * 32 + j];
    float sn = fsin[i * 32 + j];
    float2 v = *(const float2*)(g_kvtmp + (size_t)rowg * 2048 + h * 64 + 2 * j);
    float2 o;
    o.x = v.x * c - v.y * sn;
    o.y = v.x * sn + v.y * c;
    *(float2*)(g_kmem + ((size_t)(b * 16 + h) * 512 + i) * 64 + 2 * j) = o;
}

__global__ void __launch_bounds__(256) scatter_vmem()
{
    int t = blockIdx.x * 256 + threadIdx.x;      // 262144
    int f = t & 255;
    int h = f >> 4, d4 = f & 15;
    int rowg = t >> 8;
    int i = rowg & 511;
    int b = rowg >> 9;
    float4 v = ((const float4*)g_kvtmp)[(size_t)rowg * 512 + 256 + f];
    ((float4*)g_vmem)[((size_t)(b * 16 + h) * 512 + i) * 16 + d4] = v;
}

// ---------------- fused causal attention (x queries only) --------------------
__global__ void __launch_bounds__(128) attn2(const float* __restrict__ Qs,
                                             const float* __restrict__ Kx,
                                             const float* __restrict__ Vx,
                                             int stepOff)
{
    __shared__ float Ksh[64 * 72];
    __shared__ float Vsh[64 * 72];
    const int bh = blockIdx.x;
    const int by = blockIdx.y;
    const int b = bh >> 4, h = bh & 15;
    const int tid = threadIdx.x;
    const int rl = tid >> 1;
    const int half = tid & 1;
    const int off = half * 36;
    const int qrow = by * 64 + rl;

    const float* qp = Qs + ((size_t)bh * 512 + qrow) * 64 + half * 32;
    float q[32];
#pragma unroll
    for (int d = 0; d < 32; d += 4) {
        float4 v = *(const float4*)(qp + d);
        q[d] = v.x; q[d + 1] = v.y; q[d + 2] = v.z; q[d + 3] = v.w;
    }
    float O[32];
#pragma unroll
    for (int d = 0; d < 32; d++) O[d] = 0.f;
    float m = -1e30f, l = 0.f;

    const int nkt = 9 + by;
    for (int kt = 0; kt < nkt; kt++) {
        const float* ksrc = (kt < 8) ? (g_kmem + ((size_t)bh * 512 + kt * 64) * 64)
                                     : (Kx + ((size_t)bh * 512 + (kt - 8) * 64) * 64);
        const float* vsrc = (kt < 8) ? (g_vmem + ((size_t)bh * 512 + kt * 64) * 64)
                                     : (Vx + ((size_t)bh * 512 + (kt - 8) * 64) * 64);
        __syncthreads();
#pragma unroll
        for (int i = 0; i < 8; i++) {
            int idx = i * 128 + tid;
            int row = idx >> 4, c4 = idx & 15;
            int dst = row * 72 + c4 * 4 + (c4 >= 8 ? 4 : 0);
            *(float4*)(Ksh + dst) = ((const float4*)ksrc)[idx];
            *(float4*)(Vsh + dst) = ((const float4*)vsrc)[idx];
        }
        __syncthreads();
        const bool diag = (kt == 8 + by);
#pragma unroll 1
        for (int c = 0; c < 4; c++) {
            float sreg[16];
            float mt = -1e30f;
#pragma unroll
            for (int j = 0; j < 16; j++) {
                const float* kr = Ksh + (c * 16 + j) * 72 + off;
                float p = 0.f;
#pragma unroll
                for (int d = 0; d < 32; d += 4) {
                    float4 k4 = *(const float4*)(kr + d);
                    p += q[d] * k4.x + q[d + 1] * k4.y + q[d + 2] * k4.z + q[d + 3] * k4.w;
                }
                p += __shfl_xor_sync(0xffffffffu, p, 1);
                float sj = p * 0.125f;
                if (diag && (c * 16 + j) > rl) sj = -1e30f;
                sreg[j] = sj;
                mt = fmaxf(mt, sj);
            }
            float mnew = fmaxf(m, mt);
            float corr = __expf(m - mnew);
            l *= corr;
#pragma unroll
            for (int d = 0; d < 32; d++) O[d] *= corr;
#pragma unroll
            for (int j = 0; j < 16; j++) {
                float pj = __expf(sreg[j] - mnew);
                l += pj;
                const float* vr = Vsh + (c * 16 + j) * 72 + off;
#pragma unroll
                for (int d = 0; d < 32; d += 4) {
                    float4 v4 = *(const float4*)(vr + d);
                    O[d]     += pj * v4.x;
                    O[d + 1] += pj * v4.y;
                    O[d + 2] += pj * v4.z;
                    O[d + 3] += pj * v4.w;
                }
            }
            m = mnew;
        }
    }

    float inv = 1.0f / l;
    size_t o1 = ((size_t)b * S_ + stepOff + qrow) * D_ + h * 64 + half * 32;
    size_t o2 = ((size_t)(b * 512 + qrow)) * D_ + h * 64 + half * 32;
#pragma unroll
    for (int d = 0; d < 32; d += 2) {
        float v0 = O[d] * inv, v1 = O[d + 1] * inv;
        __half h0, l0, h1, l1;
        splith(v0, h0, l0);
        splith(v1, h1, l1);
        __half2 hh = __halves2half2(h0, h1);
        __half2 ll = __halves2half2(l0, l1);
        *(__half2*)(g_outh + o1 + d) = hh;
        *(__half2*)(g_outl + o1 + d) = ll;
        *(__half2*)(g_omh + o2 + d) = hh;
        *(__half2*)(g_oml + o2 + d) = ll;
    }
}

// ---------------- host driver ------------------------------------------------
static void* symp(const void* s) { void* p; cudaGetSymbolAddress(&p, s); return p; }

extern "C" void kernel_launch(void* const* d_in, const int* in_sizes, int n_in,
                              void* d_out, int out_size)
{
    (void)in_sizes; (void)n_in; (void)out_size;
    const float* x    = (const float*)d_in[0];
    const float* fcos = (const float*)d_in[1];
    const float* fsin = (const float*)d_in[2];
    const float* wq   = (const float*)d_in[3];
    const float* wk   = (const float*)d_in[4];
    const float* wv   = (const float*)d_in[5];
    const float* wo   = (const float*)d_in[6];
    const float* wm   = (const float*)d_in[7];
    const float* wkm  = (const float*)d_in[8];
    const float* wvm  = (const float*)d_in[9];
    const float* w1   = (const float*)d_in[10];
    const float* w3   = (const float*)d_in[11];
    const float* w2   = (const float*)d_in[12];
    const float* ffnw = (const float*)d_in[13];
    const float* memw = (const float*)d_in[14];
    const float* om0  = (const float*)d_in[15];
    float* outp = (float*)d_out;

    static bool attrDone = false;
    if (!attrDone) {
        cudaFuncSetAttribute(gemm_hs, cudaFuncAttributeMaxDynamicSharedMemorySize, HSM_BYTES);
        attrDone = true;
    }

    __half *wqkvTh = (__half*)symp(g_wqkvTh), *wqkvTl = (__half*)symp(g_wqkvTl);
    __half *w13Th = (__half*)symp(g_w13Th), *w13Tl = (__half*)symp(g_w13Tl);
    __half *wkvmTh = (__half*)symp(g_wkvmTh), *wkvmTl = (__half*)symp(g_wkvmTl);
    __half *wmTh = (__half*)symp(g_wmTh), *wmTl = (__half*)symp(g_wmTl);
    __half *w2Th = (__half*)symp(g_w2Th), *w2Tl = (__half*)symp(g_w2Tl);
    __half *woTh = (__half*)symp(g_woTh), *woTl = (__half*)symp(g_woTl);
    __half *xh = (__half*)symp(g_xh), *xl = (__half*)symp(g_xl);
    __half *omh = (__half*)symp(g_omh), *oml = (__half*)symp(g_oml);
    __half *th = (__half*)symp(g_th), *tl = (__half*)symp(g_tl);
    __half *om3h = (__half*)symp(g_om3h), *om3l = (__half*)symp(g_om3l);
    __half *gh = (__half*)symp(g_gh), *gl = (__half*)symp(g_gl);
    __half *outh = (__half*)symp(g_outh), *outl = (__half*)symp(g_outl);
    float *xqkv = (float*)symp(g_xqkv);
    float *qall = (float*)symp(g_qall), *kxall = (float*)symp(g_kxall), *vxall = (float*)symp(g_vxall);
    float *om2 = (float*)symp(g_om2), *hbuf = (float*)symp(g_hbuf);
    float *kvtmp = (float*)symp(g_kvtmp);

    // ---- weight transpose+split / input split (per launch) ----
    wsplitT<<<dim3(32, 32), 256>>>(wq, wqkvTh, wqkvTl, 1024, 1024);
    wsplitT<<<dim3(32, 32), 256>>>(wk, wqkvTh + 1024 * 1024, wqkvTl + 1024 * 1024, 1024, 1024);
    wsplitT<<<dim3(32, 32), 256>>>(wv, wqkvTh + 2048 * 1024, wqkvTl + 2048 * 1024, 1024, 1024);
    wsplitT<<<dim3(88, 32), 256>>>(w1, w13Th, w13Tl, 1024, 2816);
    wsplitT<<<dim3(88, 32), 256>>>(w3, w13Th + 2816 * 1024, w13Tl + 2816 * 1024, 1024, 2816);
    wsplitT<<<dim3(32, 32), 256>>>(wkm, wkvmTh, wkvmTl, 1024, 1024);
    wsplitT<<<dim3(32, 32), 256>>>(wvm, wkvmTh + 1024 * 1024, wkvmTl + 1024 * 1024, 1024, 1024);
    wsplitT<<<dim3(32, 32), 256>>>(wm, wmTh, wmTl, 1024, 1024);
    wsplitT<<<dim3(32, 88), 256>>>(w2, w2Th, w2Tl, 2816, 1024);
    wsplitT<<<dim3(32, 32), 256>>>(wo, woTh, woTl, 1024, 1024);
    asplit<<<8192, 256>>>(x, xh, xl, B_ * S_ * D_ / 4);
    init_om_split<<<4096, 256>>>(om0);

    // ---- batched x-branch ----
    gemm_hs<<<dim3(48, 64), 256, HSM_BYTES>>>(xh, xl, wqkvTh, wqkvTl, xqkv, 3072, 1024, 0);
    rope_all<<<16384, 256>>>(fcos, fsin, qall, 0);
    rope_all<<<16384, 256>>>(fcos, fsin, kxall, 1024);
    scatter_all_v<<<8192, 256>>>();

    const size_t stepSz = (size_t)B_ * H_ * M_ * HD_;
    for (int s = 0; s < NSTEP; s++) {
        gemm_hs<<<dim3(16, 8), 256, HSM_BYTES>>>(omh, oml, wmTh, wmTl, om2, 1024, 1024, 0);
        rmsnorm_split<<<1024, 256>>>(om2, ffnw, th, tl);
        gemm_hs<<<dim3(88, 8), 256, HSM_BYTES>>>(th, tl, w13Th, w13Tl, hbuf, 5632, 1024, 0);
        silu_split<<<dim3(3, 1024), 256>>>(hbuf, gh, gl);
        gemm_hs<<<dim3(16, 8), 256, HSM_BYTES>>>(gh, gl, w2Th, w2Tl, om2, 1024, 2816, 1);
        rmsnorm_split<<<1024, 256>>>(om2, memw, om3h, om3l);
        gemm_hs<<<dim3(32, 8), 256, HSM_BYTES>>>(om3h, om3l, wkvmTh, wkvmTl, kvtmp, 2048, 1024, 0);
        rope_mem<<<2048, 256>>>(fcos, fsin);
        scatter_vmem<<<1024, 256>>>();
        attn2<<<dim3(B_ * H_, 8), 128>>>(qall + s * stepSz, kxall + s * stepSz,
                                         vxall + s * stepSz, s * M_);
    }

    // ---- final projection ----
    gemm_hs<<<dim3(16, 64), 256, HSM_BYTES>>>(outh, outl, woTh, woTl, outp, 1024, 1024, 0);
}

// round 11
// speedup vs baseline: 2.8236x; 1.0767x over previous
#include <cuda_runtime.h>
#include <cuda_fp16.h>
#include <stdint.h>
#include <math.h>

#define B_ 2
#define S_ 4096
#define D_ 1024
#define H_ 16
#define HD_ 64
#define M_ 512
#define L_ 1024
#define HID_ 2816
#define NSTEP 8

// ---------------- scratch (static device globals; no allocs) ----------------
__device__ __align__(16) __half g_wqkvTh[3*D_*D_], g_wqkvTl[3*D_*D_];
__device__ __align__(16) __half g_w13Th [2*HID_*D_], g_w13Tl [2*HID_*D_];
__device__ __align__(16) __half g_wkvmTh[2*D_*D_], g_wkvmTl[2*D_*D_];
__device__ __align__(16) __half g_wmTh  [D_*D_],  g_wmTl  [D_*D_];
__device__ __align__(16) __half g_w2Th  [D_*HID_], g_w2Tl [D_*HID_];
__device__ __align__(16) __half g_woTh  [D_*D_],  g_woTl  [D_*D_];
__device__ __align__(16) __half g_xh [B_*S_*D_],  g_xl [B_*S_*D_];
__device__ __align__(16) __half g_omh[B_*M_*D_],  g_oml[B_*M_*D_];
__device__ __align__(16) __half g_th [B_*M_*D_],  g_tl [B_*M_*D_];
__device__ __align__(16) __half g_om3h[B_*M_*D_], g_om3l[B_*M_*D_];
__device__ __align__(16) __half g_gh [B_*M_*HID_], g_gl [B_*M_*HID_];
__device__ __align__(16) __half g_outh[B_*S_*D_], g_outl[B_*S_*D_];
__device__ float g_xqkv [B_*S_*3*D_];
__device__ float g_qall [NSTEP*B_*H_*M_*HD_];
__device__ float g_kxall[NSTEP*B_*H_*M_*HD_];
__device__ float g_vxall[NSTEP*B_*H_*M_*HD_];
__device__ float g_om2  [B_*M_*D_];
__device__ float g_hbuf [B_*M_*2*HID_];
__device__ float g_kvtmp[B_*M_*2*D_];
__device__ float g_kmem [B_*H_*M_*HD_], g_vmem[B_*H_*M_*HD_];

// ---------------- helpers ----------------------------------------------------
__device__ __forceinline__ void splith(float v, __half& h, __half& l) {
    h = __float2half_rn(v);
    l = __float2half_rn((v - __half2float(h)) * 2048.0f);
}

__device__ __forceinline__ void hmma(float* c, const uint32_t* a, const uint32_t* b)
{
    asm volatile("mma.sync.aligned.m16n8k16.row.col.f32.f16.f16.f32 "
                 "{%0,%1,%2,%3}, {%4,%5,%6,%7}, {%8,%9}, {%0,%1,%2,%3};"
                 : "+f"(c[0]), "+f"(c[1]), "+f"(c[2]), "+f"(c[3])
                 : "r"(a[0]), "r"(a[1]), "r"(a[2]), "r"(a[3]), "r"(b[0]), "r"(b[1]));
}

__device__ __forceinline__ void cpa16(uint8_t* dst, const void* src) {
    unsigned d = (unsigned)__cvta_generic_to_shared(dst);
    asm volatile("cp.async.cg.shared.global [%0], [%1], 16;" :: "r"(d), "l"(src));
}

__device__ __forceinline__ void ldm4(uint32_t* r, uint32_t addr) {
    asm volatile("ldmatrix.sync.aligned.m8n8.x4.shared.b16 {%0,%1,%2,%3}, [%4];"
                 : "=r"(r[0]), "=r"(r[1]), "=r"(r[2]), "=r"(r[3]) : "r"(addr));
}

// ---------------- fp16-split tensor GEMM (mma.sync + ldmatrix, 3-stage) ------
// C[M,Ntot] = (Ah + Al/2048) @ (Bh + Bl/2048)^T
// CTA tile 128x64, BK=32 halves, 256 threads (8 warps 4x2), warp tile 32x32.
#define HBM 128
#define HBN 64
#define HBK 32
#define ROWB 80            // bytes per smem row (32 halves + 8 pad)
#define STG_AH 0
#define STG_AL 10240
#define STG_BH 20480
#define STG_BL 25600
#define STG_SZ 30720
#define HSM_BYTES (3 * STG_SZ)

__global__ void __launch_bounds__(256, 2)
gemm_hs(const __half* __restrict__ Ah, const __half* __restrict__ Al,
        const __half* __restrict__ Bh, const __half* __restrict__ Bl,
        float* __restrict__ C, int Ntot, int K, int accum)
{
    extern __shared__ uint8_t dyn[];
    const uint32_t sb = (uint32_t)__cvta_generic_to_shared(dyn);
    const int tid = threadIdx.x, lane = tid & 31, wid = tid >> 5;
    const int grp = lane >> 2, qk = lane & 3;
    const int wm = (wid >> 1) * 32, wn = (wid & 1) * 32;
    const int bm0 = blockIdx.y * HBM, bn0 = blockIdx.x * HBN;

    // ldmatrix lane-address components
    const int aRow = (lane & 7) + ((lane >> 3) & 1) * 8;
    const int aCol = ((lane >> 4) & 1) * 16;
    const int bRow = (lane & 7) + ((lane >> 4) & 1) * 8;
    const int bCol = ((lane >> 3) & 1) * 16;

    float acc0[2][4][4], acc1[2][4][4];
#pragma unroll
    for (int i = 0; i < 2; i++)
#pragma unroll
        for (int j = 0; j < 4; j++)
#pragma unroll
            for (int e = 0; e < 4; e++) { acc0[i][j][e] = 0.f; acc1[i][j][e] = 0.f; }

    auto issue = [&](int ci) {
        int p = ci % 3;
        int k0 = ci * HBK;
        uint8_t* dAh = dyn + p * STG_SZ + STG_AH;
        uint8_t* dAl = dyn + p * STG_SZ + STG_AL;
        uint8_t* dBh = dyn + p * STG_SZ + STG_BH;
        uint8_t* dBl = dyn + p * STG_SZ + STG_BL;
#pragma unroll
        for (int i = 0; i < 2; i++) {
            int idx = tid + i * 256;            // 512 chunks of 16B (A)
            int row = idx >> 2, c16 = idx & 3;
            size_t go = (size_t)(bm0 + row) * K + k0 + c16 * 8;
            cpa16(dAh + row * ROWB + c16 * 16, Ah + go);
            cpa16(dAl + row * ROWB + c16 * 16, Al + go);
        }
        {
            int row = tid >> 2, c16 = tid & 3;  // 256 chunks (B)
            size_t go = (size_t)(bn0 + row) * K + k0 + c16 * 8;
            cpa16(dBh + row * ROWB + c16 * 16, Bh + go);
            cpa16(dBl + row * ROWB + c16 * 16, Bl + go);
        }
        asm volatile("cp.async.commit_group;");
    };

    const int nch = K / HBK;
    issue(0);
    if (nch > 1) issue(1);

    for (int st = 0; st < nch; st++) {
        if (st + 1 < nch) {
            asm volatile("cp.async.wait_group 1;");
        } else {
            asm volatile("cp.async.wait_group 0;");
        }
        __syncthreads();
        if (st + 2 < nch) issue(st + 2);

        int p = st % 3;
        uint32_t baseA = sb + p * STG_SZ;
        uint32_t baseB = sb + p * STG_SZ;
#pragma unroll
        for (int s16 = 0; s16 < 2; s16++) {
            const int cb0 = s16 * 32;
            uint32_t ah[2][4], al[2][4], bh[4][2], bl[4][2];
#pragma unroll
            for (int mt = 0; mt < 2; mt++) {
                uint32_t ad = baseA + STG_AH + (wm + mt * 16 + aRow) * ROWB + cb0 + aCol;
                ldm4(ah[mt], ad);
                ldm4(al[mt], ad + (STG_AL - STG_AH));
            }
#pragma unroll
            for (int g = 0; g < 2; g++) {
                uint32_t tmp[4];
                uint32_t bd = baseB + STG_BH + (wn + g * 16 + bRow) * ROWB + cb0 + bCol;
                ldm4(tmp, bd);
                bh[2 * g][0] = tmp[0]; bh[2 * g][1] = tmp[1];
                bh[2 * g + 1][0] = tmp[2]; bh[2 * g + 1][1] = tmp[3];
                ldm4(tmp, bd + (STG_BL - STG_BH));
                bl[2 * g][0] = tmp[0]; bl[2 * g][1] = tmp[1];
                bl[2 * g + 1][0] = tmp[2]; bl[2 * g + 1][1] = tmp[3];
            }
#pragma unroll
            for (int mt = 0; mt < 2; mt++)
#pragma unroll
                for (int nt = 0; nt < 4; nt++) {
                    hmma(acc0[mt][nt], ah[mt], bh[nt]);
                    hmma(acc1[mt][nt], ah[mt], bl[nt]);
                    hmma(acc1[mt][nt], al[mt], bh[nt]);
                }
        }
    }

    const float isc = 4.8828125e-4f;   // 1/2048
#pragma unroll
    for (int mt = 0; mt < 2; mt++) {
        int r0 = bm0 + wm + mt * 16 + grp;
#pragma unroll
        for (int nt = 0; nt < 4; nt++) {
            int c0 = bn0 + wn + nt * 8 + 2 * qk;
            float v0 = acc0[mt][nt][0] + acc1[mt][nt][0] * isc;
            float v1 = acc0[mt][nt][1] + acc1[mt][nt][1] * isc;
            float v2 = acc0[mt][nt][2] + acc1[mt][nt][2] * isc;
            float v3 = acc0[mt][nt][3] + acc1[mt][nt][3] * isc;
            float2* p0 = (float2*)(C + (size_t)r0 * Ntot + c0);
            float2* p1 = (float2*)(C + (size_t)(r0 + 8) * Ntot + c0);
            float2 w0 = make_float2(v0, v1), w1 = make_float2(v2, v3);
            if (accum) {
                float2 o0 = *p0, o1 = *p1;
                w0.x += o0.x; w0.y += o0.y; w1.x += o1.x; w1.y += o1.y;
            }
            *p0 = w0;
            *p1 = w1;
        }
    }
}

// ---------------- weight transpose + split: w[K][N] -> out[N][K] -------------
__global__ void __launch_bounds__(256) wsplitT(const float* __restrict__ w,
                                               __half* __restrict__ bh,
                                               __half* __restrict__ bl,
                                               int K, int N)
{
    __shared__ float t[32][33];
    int n0 = blockIdx.x * 32, k0 = blockIdx.y * 32;
    int tx = threadIdx.x & 31, ty = threadIdx.x >> 5;
#pragma unroll
    for (int i = 0; i < 4; i++)
        t[ty + i * 8][tx] = w[(size_t)(k0 + ty + i * 8) * N + n0 + tx];
    __syncthreads();
#pragma unroll
    for (int i = 0; i < 4; i++) {
        int nn = ty + i * 8;
        float v = t[tx][nn];
        __half h, l;
        splith(v, h, l);
        bh[(size_t)(n0 + nn) * K + k0 + tx] = h;
        bl[(size_t)(n0 + nn) * K + k0 + tx] = l;
    }
}

// ---------------- activation split (no transpose) ----------------------------
__global__ void __launch_bounds__(256) asplit(const float* __restrict__ in,
                                              __half* __restrict__ oh,
                                              __half* __restrict__ ol, int n4)
{
    int i = blockIdx.x * 256 + threadIdx.x;
    if (i >= n4) return;
    float4 v = ((const float4*)in)[i];
    __half h0, l0, h1, l1, h2, l2, h3, l3;
    splith(v.x, h0, l0); splith(v.y, h1, l1);
    splith(v.z, h2, l2); splith(v.w, h3, l3);
    ((__half2*)oh)[i * 2]     = __halves2half2(h0, h1);
    ((__half2*)oh)[i * 2 + 1] = __halves2half2(h2, h3);
    ((__half2*)ol)[i * 2]     = __halves2half2(l0, l1);
    ((__half2*)ol)[i * 2 + 1] = __halves2half2(l2, l3);
}

__global__ void __launch_bounds__(256) init_om_split(const float* __restrict__ om0)
{
    int t = blockIdx.x * 256 + threadIdx.x;     // 2*512*1024
    int d = t & 1023;
    int i = (t >> 10) & 511;
    __half h, l;
    splith(om0[i * 1024 + d], h, l);
    g_omh[t] = h; g_oml[t] = l;
}

// ---------------- rmsnorm -> split -------------------------------------------
__global__ void __launch_bounds__(256) rmsnorm_split(const float* __restrict__ in,
                                                     const float* __restrict__ w,
                                                     __half* __restrict__ oh,
                                                     __half* __restrict__ ol)
{
    const int row = blockIdx.x;
    const int t = threadIdx.x;
    float4 v = ((const float4*)(in + (size_t)row * D_))[t];
    float ss = v.x * v.x + v.y * v.y + v.z * v.z + v.w * v.w;
#pragma unroll
    for (int o = 16; o; o >>= 1) ss += __shfl_xor_sync(0xffffffffu, ss, o);
    __shared__ float sred[8];
    if ((t & 31) == 0) sred[t >> 5] = ss;
    __syncthreads();
    float tot = 0.f;
#pragma unroll
    for (int i = 0; i < 8; i++) tot += sred[i];
    float rs = rsqrtf(tot * (1.0f / (float)D_) + 1e-5f);
    float4 wv = ((const float4*)w)[t];
    float y0 = v.x * rs * wv.x, y1 = v.y * rs * wv.y;
    float y2 = v.z * rs * wv.z, y3 = v.w * rs * wv.w;
    __half h0, l0, h1, l1, h2, l2, h3, l3;
    splith(y0, h0, l0); splith(y1, h1, l1); splith(y2, h2, l2); splith(y3, h3, l3);
    __half2* ph = (__half2*)(oh + (size_t)row * D_);
    __half2* pl = (__half2*)(ol + (size_t)row * D_);
    ph[t * 2]     = __halves2half2(h0, h1);
    ph[t * 2 + 1] = __halves2half2(h2, h3);
    pl[t * 2]     = __halves2half2(l0, l1);
    pl[t * 2 + 1] = __halves2half2(l2, l3);
}

// ---------------- silu -> split ----------------------------------------------
__global__ void __launch_bounds__(256) silu_split(const float* __restrict__ hb,
                                                  __half* __restrict__ gh,
                                                  __half* __restrict__ gl)
{
    int c4 = blockIdx.x * 256 + threadIdx.x;     // 0..703
    if (c4 >= HID_ / 4) return;
    int row = blockIdx.y;
    const float* rp = hb + (size_t)row * (2 * HID_);
    float4 a = ((const float4*)rp)[c4];
    float4 b = ((const float4*)(rp + HID_))[c4];
    float g0 = a.x / (1.f + __expf(-a.x)) * b.x;
    float g1 = a.y / (1.f + __expf(-a.y)) * b.y;
    float g2 = a.z / (1.f + __expf(-a.z)) * b.z;
    float g3 = a.w / (1.f + __expf(-a.w)) * b.w;
    __half h0, l0, h1, l1, h2, l2, h3, l3;
    splith(g0, h0, l0); splith(g1, h1, l1); splith(g2, h2, l2); splith(g3, h3, l3);
    __half2* ph = (__half2*)(gh + (size_t)row * HID_);
    __half2* pl = (__half2*)(gl + (size_t)row * HID_);
    ph[c4 * 2]     = __halves2half2(h0, h1);
    ph[c4 * 2 + 1] = __halves2half2(h2, h3);
    pl[c4 * 2]     = __halves2half2(l0, l1);
    pl[c4 * 2 + 1] = __halves2half2(l2, l3);
}

// ---------------- rope / scatter ---------------------------------------------
__global__ void __launch_bounds__(256) rope_all(const float* __restrict__ fcos,
                                                const float* __restrict__ fsin,
                                                float* __restrict__ out, int colOff)
{
    int t = blockIdx.x * 256 + threadIdx.x;      // 4194304
    int j = t & 31;
    int h = (t >> 5) & 15;
    int rowg = t >> 9;
    int i = rowg & 511;
    int s = (rowg >> 9) & 7;
    int b = rowg >> 12;
    int pos = M_ + i;
    float c = fcos[pos * 32 + j];
    float sn = fsin[pos * 32 + j];
    float2 v = *(const float2*)(g_xqkv + (size_t)rowg * 3072 + colOff + h * 64 + 2 * j);
    float2 o;
    o.x = v.x * c - v.y * sn;
    o.y = v.x * sn + v.y * c;
    *(float2*)(out + (size_t)s * (B_*H_*M_*HD_) + (((size_t)(b * 16 + h) * 512 + i) * 64 + 2 * j)) = o;
}

__global__ void __launch_bounds__(256) scatter_all_v()
{
    int t = blockIdx.x * 256 + threadIdx.x;      // 2097152
    int f = t & 255;
    int h = f >> 4, d4 = f & 15;
    int rowg = t >> 8;
    int i = rowg & 511;
    int s = (rowg >> 9) & 7;
    int b = rowg >> 12;
    float4 v = ((const float4*)g_xqkv)[(size_t)rowg * 768 + 512 + f];
    ((float4*)g_vxall)[(size_t)s * (B_*H_*M_*HD_/4) + ((size_t)(b * 16 + h) * 512 + i) * 16 + d4] = v;
}

__global__ void __launch_bounds__(256) rope_mem(const float* __restrict__ fcos,
                                                const float* __restrict__ fsin)
{
    int t = blockIdx.x * 256 + threadIdx.x;      // 524288
    int j = t & 31;
    int h = (t >> 5) & 15;
    int rowg = t >> 9;
    int i = rowg & 511;
    int b = rowg >> 9;
    float c = fcos[i * 32 + j];
    float sn = fsin[i * 32 + j];
    float2 v = *(const float2*)(g_kvtmp + (size_t)rowg * 2048 + h * 64 + 2 * j);
    float2 o;
    o.x = v.x * c - v.y * sn;
    o.y = v.x * sn + v.y * c;
    *(float2*)(g_kmem + ((size_t)(b * 16 + h) * 512 + i) * 64 + 2 * j) = o;
}

__global__ void __launch_bounds__(256) scatter_vmem()
{
    int t = blockIdx.x * 256 + threadIdx.x;      // 262144
    int f = t & 255;
    int h = f >> 4, d4 = f & 15;
    int rowg = t >> 8;
    int i = rowg & 511;
    int b = rowg >> 9;
    float4 v = ((const float4*)g_kvtmp)[(size_t)rowg * 512 + 256 + f];
    ((float4*)g_vmem)[((size_t)(b * 16 + h) * 512 + i) * 16 + d4] = v;
}

// ---------------- fused causal attention (x queries only) --------------------
__global__ void __launch_bounds__(128) attn2(const float* __restrict__ Qs,
                                             const float* __restrict__ Kx,
                                             const float* __restrict__ Vx,
                                             int stepOff)
{
    __shared__ float Ksh[64 * 72];
    __shared__ float Vsh[64 * 72];
    const int bh = blockIdx.x;
    const int by = blockIdx.y;
    const int b = bh >> 4, h = bh & 15;
    const int tid = threadIdx.x;
    const int rl = tid >> 1;
    const int half = tid & 1;
    const int off = half * 36;
    const int qrow = by * 64 + rl;

    const float* qp = Qs + ((size_t)bh * 512 + qrow) * 64 + half * 32;
    float q[32];
#pragma unroll
    for (int d = 0; d < 32; d += 4) {
        float4 v = *(const float4*)(qp + d);
        q[d] = v.x; q[d + 1] = v.y; q[d + 2] = v.z; q[d + 3] = v.w;
    }
    float O[32];
#pragma unroll
    for (int d = 0; d < 32; d++) O[d] = 0.f;
    float m = -1e30f, l = 0.f;

    const int nkt = 9 + by;
    for (int kt = 0; kt < nkt; kt++) {
        const float* ksrc = (kt < 8) ? (g_kmem + ((size_t)bh * 512 + kt * 64) * 64)
                                     : (Kx + ((size_t)bh * 512 + (kt - 8) * 64) * 64);
        const float* vsrc = (kt < 8) ? (g_vmem + ((size_t)bh * 512 + kt * 64) * 64)
                                     : (Vx + ((size_t)bh * 512 + (kt - 8) * 64) * 64);
        __syncthreads();
#pragma unroll
        for (int i = 0; i < 8; i++) {
            int idx = i * 128 + tid;
            int row = idx >> 4, c4 = idx & 15;
            int dst = row * 72 + c4 * 4 + (c4 >= 8 ? 4 : 0);
            *(float4*)(Ksh + dst) = ((const float4*)ksrc)[idx];
            *(float4*)(Vsh + dst) = ((const float4*)vsrc)[idx];
        }
        __syncthreads();
        const bool diag = (kt == 8 + by);
#pragma unroll 1
        for (int c = 0; c < 4; c++) {
            float sreg[16];
            float mt = -1e30f;
#pragma unroll
            for (int j = 0; j < 16; j++) {
                const float* kr = Ksh + (c * 16 + j) * 72 + off;
                float p = 0.f;
#pragma unroll
                for (int d = 0; d < 32; d += 4) {
                    float4 k4 = *(const float4*)(kr + d);
                    p += q[d] * k4.x + q[d + 1] * k4.y + q[d + 2] * k4.z + q[d + 3] * k4.w;
                }
                p += __shfl_xor_sync(0xffffffffu, p, 1);
                float sj = p * 0.125f;
                if (diag && (c * 16 + j) > rl) sj = -1e30f;
                sreg[j] = sj;
                mt = fmaxf(mt, sj);
            }
            float mnew = fmaxf(m, mt);
            float corr = __expf(m - mnew);
            l *= corr;
#pragma unroll
            for (int d = 0; d < 32; d++) O[d] *= corr;
#pragma unroll
            for (int j = 0; j < 16; j++) {
                float pj = __expf(sreg[j] - mnew);
                l += pj;
                const float* vr = Vsh + (c * 16 + j) * 72 + off;
#pragma unroll
                for (int d = 0; d < 32; d += 4) {
                    float4 v4 = *(const float4*)(vr + d);
                    O[d]     += pj * v4.x;
                    O[d + 1] += pj * v4.y;
                    O[d + 2] += pj * v4.z;
                    O[d + 3] += pj * v4.w;
                }
            }
            m = mnew;
        }
    }

    float inv = 1.0f / l;
    size_t o1 = ((size_t)b * S_ + stepOff + qrow) * D_ + h * 64 + half * 32;
    size_t o2 = ((size_t)(b * 512 + qrow)) * D_ + h * 64 + half * 32;
#pragma unroll
    for (int d = 0; d < 32; d += 2) {
        float v0 = O[d] * inv, v1 = O[d + 1] * inv;
        __half h0, l0, h1, l1;
        splith(v0, h0, l0);
        splith(v1, h1, l1);
        __half2 hh = __halves2half2(h0, h1);
        __half2 ll = __halves2half2(l0, l1);
        *(__half2*)(g_outh + o1 + d) = hh;
        *(__half2*)(g_outl + o1 + d) = ll;
        *(__half2*)(g_omh + o2 + d) = hh;
        *(__half2*)(g_oml + o2 + d) = ll;
    }
}

// ---------------- host driver ------------------------------------------------
static void* symp(const void* s) { void* p; cudaGetSymbolAddress(&p, s); return p; }

extern "C" void kernel_launch(void* const* d_in, const int* in_sizes, int n_in,
                              void* d_out, int out_size)
{
    (void)in_sizes; (void)n_in; (void)out_size;
    const float* x    = (const float*)d_in[0];
    const float* fcos = (const float*)d_in[1];
    const float* fsin = (const float*)d_in[2];
    const float* wq   = (const float*)d_in[3];
    const float* wk   = (const float*)d_in[4];
    const float* wv   = (const float*)d_in[5];
    const float* wo   = (const float*)d_in[6];
    const float* wm   = (const float*)d_in[7];
    const float* wkm  = (const float*)d_in[8];
    const float* wvm  = (const float*)d_in[9];
    const float* w1   = (const float*)d_in[10];
    const float* w3   = (const float*)d_in[11];
    const float* w2   = (const float*)d_in[12];
    const float* ffnw = (const float*)d_in[13];
    const float* memw = (const float*)d_in[14];
    const float* om0  = (const float*)d_in[15];
    float* outp = (float*)d_out;

    static bool attrDone = false;
    if (!attrDone) {
        cudaFuncSetAttribute(gemm_hs, cudaFuncAttributeMaxDynamicSharedMemorySize, HSM_BYTES);
        attrDone = true;
    }

    __half *wqkvTh = (__half*)symp(g_wqkvTh), *wqkvTl = (__half*)symp(g_wqkvTl);
    __half *w13Th = (__half*)symp(g_w13Th), *w13Tl = (__half*)symp(g_w13Tl);
    __half *wkvmTh = (__half*)symp(g_wkvmTh), *wkvmTl = (__half*)symp(g_wkvmTl);
    __half *wmTh = (__half*)symp(g_wmTh), *wmTl = (__half*)symp(g_wmTl);
    __half *w2Th = (__half*)symp(g_w2Th), *w2Tl = (__half*)symp(g_w2Tl);
    __half *woTh = (__half*)symp(g_woTh), *woTl = (__half*)symp(g_woTl);
    __half *xh = (__half*)symp(g_xh), *xl = (__half*)symp(g_xl);
    __half *omh = (__half*)symp(g_omh), *oml = (__half*)symp(g_oml);
    __half *th = (__half*)symp(g_th), *tl = (__half*)symp(g_tl);
    __half *om3h = (__half*)symp(g_om3h), *om3l = (__half*)symp(g_om3l);
    __half *gh = (__half*)symp(g_gh), *gl = (__half*)symp(g_gl);
    __half *outh = (__half*)symp(g_outh), *outl = (__half*)symp(g_outl);
    float *xqkv = (float*)symp(g_xqkv);
    float *qall = (float*)symp(g_qall), *kxall = (float*)symp(g_kxall), *vxall = (float*)symp(g_vxall);
    float *om2 = (float*)symp(g_om2), *hbuf = (float*)symp(g_hbuf);
    float *kvtmp = (float*)symp(g_kvtmp);

    // ---- weight transpose+split / input split (per launch) ----
    wsplitT<<<dim3(32, 32), 256>>>(wq, wqkvTh, wqkvTl, 1024, 1024);
    wsplitT<<<dim3(32, 32), 256>>>(wk, wqkvTh + 1024 * 1024, wqkvTl + 1024 * 1024, 1024, 1024);
    wsplitT<<<dim3(32, 32), 256>>>(wv, wqkvTh + 2048 * 1024, wqkvTl + 2048 * 1024, 1024, 1024);
    wsplitT<<<dim3(88, 32), 256>>>(w1, w13Th, w13Tl, 1024, 2816);
    wsplitT<<<dim3(88, 32), 256>>>(w3, w13Th + 2816 * 1024, w13Tl + 2816 * 1024, 1024, 2816);
    wsplitT<<<dim3(32, 32), 256>>>(wkm, wkvmTh, wkvmTl, 1024, 1024);
    wsplitT<<<dim3(32, 32), 256>>>(wvm, wkvmTh + 1024 * 1024, wkvmTl + 1024 * 1024, 1024, 1024);
    wsplitT<<<dim3(32, 32), 256>>>(wm, wmTh, wmTl, 1024, 1024);
    wsplitT<<<dim3(32, 88), 256>>>(w2, w2Th, w2Tl, 2816, 1024);
    wsplitT<<<dim3(32, 32), 256>>>(wo, woTh, woTl, 1024, 1024);
    asplit<<<8192, 256>>>(x, xh, xl, B_ * S_ * D_ / 4);
    init_om_split<<<4096, 256>>>(om0);

    // ---- batched x-branch ----
    gemm_hs<<<dim3(48, 64), 256, HSM_BYTES>>>(xh, xl, wqkvTh, wqkvTl, xqkv, 3072, 1024, 0);
    rope_all<<<16384, 256>>>(fcos, fsin, qall, 0);
    rope_all<<<16384, 256>>>(fcos, fsin, kxall, 1024);
    scatter_all_v<<<8192, 256>>>();

    const size_t stepSz = (size_t)B_ * H_ * M_ * HD_;
    for (int s = 0; s < NSTEP; s++) {
        gemm_hs<<<dim3(16, 8), 256, HSM_BYTES>>>(omh, oml, wmTh, wmTl, om2, 1024, 1024, 0);
        rmsnorm_split<<<1024, 256>>>(om2, ffnw, th, tl);
        gemm_hs<<<dim3(88, 8), 256, HSM_BYTES>>>(th, tl, w13Th, w13Tl, hbuf, 5632, 1024, 0);
        silu_split<<<dim3(3, 1024), 256>>>(hbuf, gh, gl);
        gemm_hs<<<dim3(16, 8), 256, HSM_BYTES>>>(gh, gl, w2Th, w2Tl, om2, 1024, 2816, 1);
        rmsnorm_split<<<1024, 256>>>(om2, memw, om3h, om3l);
        gemm_hs<<<dim3(32, 8), 256, HSM_BYTES>>>(om3h, om3l, wkvmTh, wkvmTl, kvtmp, 2048, 1024, 0);
        rope_mem<<<2048, 256>>>(fcos, fsin);
        scatter_vmem<<<1024, 256>>>();
        attn2<<<dim3(B_ * H_, 8), 128>>>(qall + s * stepSz, kxall + s * stepSz,
                                         vxall + s * stepSz, s * M_);
    }

    // ---- final projection ----
    gemm_hs<<<dim3(16, 64), 256, HSM_BYTES>>>(outh, outl, woTh, woTl, outp, 1024, 1024, 0);
}